// round 1
// baseline (speedup 1.0000x reference)
#include <cuda_runtime.h>

#define N_ROWS 16384
#define C_DIM 1024
#define D_FF 4096
#define NTILES 4
#define TILE_UP 1024
#define TILE_DOWN 256

// ---- device scratch (allocation-free rule: static __device__ globals) ----
__device__ float g_sig[NTILES * C_DIM];
__device__ int   g_cnt[NTILES];
__device__ int   g_rows[NTILES * N_ROWS];
__device__ float g_hidden[(size_t)N_ROWS * TILE_UP];   // 64 MB scratch

// ---------------------------------------------------------------------------
// Zero the dense output region (3/4 of columns must be exactly 0; buffer is
// poisoned). 16,777,216 floats = 4,194,304 float4.
// ---------------------------------------------------------------------------
__global__ void zero_out_kernel(float4* __restrict__ out) {
    out[(size_t)blockIdx.x * 256 + threadIdx.x] = make_float4(0.f, 0.f, 0.f, 0.f);
}

// ---------------------------------------------------------------------------
// Tile signatures: sig[t][c] = sign(sum_{r<1024} w_up[t*1024+r][c]).
// Also resets the per-expert atomic counters each replay.
// grid (4, 8), 128 threads.
// ---------------------------------------------------------------------------
__global__ void sig_kernel(const float* __restrict__ w_up) {
    if (blockIdx.x == 0 && blockIdx.y == 0 && threadIdx.x < NTILES)
        g_cnt[threadIdx.x] = 0;
    int t = blockIdx.x;
    int c = blockIdx.y * 128 + threadIdx.x;
    const float* base = w_up + (size_t)t * TILE_UP * C_DIM + c;
    float s = 0.f;
    #pragma unroll 8
    for (int r = 0; r < TILE_UP; r++) s += base[(size_t)r * C_DIM];
    g_sig[t * C_DIM + c] = (s > 0.f) ? 1.f : ((s < 0.f) ? -1.f : 0.f);
}

// ---------------------------------------------------------------------------
// Routing: per-row fp32 scores vs 4 signatures, argmax (first-max tie-break,
// matching jnp.argmax), gather row into winner's list, emit one-hot gate.
// One block of 128 threads per row.
// ---------------------------------------------------------------------------
__global__ void route_kernel(const float* __restrict__ x,
                             float* __restrict__ gate_out, int write_gate) {
    __shared__ float red[NTILES][128];
    int n = blockIdx.x;
    int tid = threadIdx.x;
    const float* xr = x + (size_t)n * C_DIM;
    float a0 = 0.f, a1 = 0.f, a2 = 0.f, a3 = 0.f;
    for (int k = tid; k < C_DIM; k += 128) {
        float xv = xr[k];
        a0 += xv * g_sig[k];
        a1 += xv * g_sig[C_DIM + k];
        a2 += xv * g_sig[2 * C_DIM + k];
        a3 += xv * g_sig[3 * C_DIM + k];
    }
    red[0][tid] = a0; red[1][tid] = a1; red[2][tid] = a2; red[3][tid] = a3;
    __syncthreads();
    for (int s = 64; s > 0; s >>= 1) {
        if (tid < s) {
            #pragma unroll
            for (int t = 0; t < NTILES; t++) red[t][tid] += red[t][tid + s];
        }
        __syncthreads();
    }
    if (tid == 0) {
        float best = red[0][0];
        int w = 0;
        #pragma unroll
        for (int t = 1; t < NTILES; t++)
            if (red[t][0] > best) { best = red[t][0]; w = t; }
        int pos = atomicAdd(&g_cnt[w], 1);
        g_rows[w * N_ROWS + pos] = n;
        if (write_gate) {
            #pragma unroll
            for (int t = 0; t < NTILES; t++)
                gate_out[(size_t)n * NTILES + t] = (t == w) ? 1.f : 0.f;
        }
    }
}

// ---------------------------------------------------------------------------
// Grouped GEMM 1 (up + bias + ReLU):
//   H[row, 0:1024] = relu( X[row,:] @ W_up[e*1024:(e+1)*1024, :]^T + b_up_e )
// for rows routed to expert e. 128x64x16 tiles, 8x4 per-thread microtile.
// grid (16 n-tiles, 128 m-tiles, 4 experts), 256 threads.
// ---------------------------------------------------------------------------
__global__ void __launch_bounds__(256)
gemm_up_kernel(const float* __restrict__ x, const float* __restrict__ w_up,
               const float* __restrict__ b_up) {
    int e = blockIdx.z;
    int cnt = g_cnt[e];
    int m0 = blockIdx.y * 128;
    if (m0 >= cnt) return;
    int n0 = blockIdx.x * 64;

    __shared__ float As[16][128];
    __shared__ float Bs[16][64];
    __shared__ int rs[128];

    int tid = threadIdx.x;
    if (tid < 128) {
        int m = m0 + tid;
        rs[tid] = (m < cnt) ? g_rows[e * N_ROWS + m] : -1;
    }
    __syncthreads();

    int ty = tid >> 4, tx = tid & 15;
    float acc[8][4];
    #pragma unroll
    for (int i = 0; i < 8; i++)
        #pragma unroll
        for (int j = 0; j < 4; j++) acc[i][j] = 0.f;

    const float* wb = w_up + (size_t)e * TILE_UP * C_DIM;

    for (int k0 = 0; k0 < C_DIM; k0 += 16) {
        // A tile: 128 rows x 16 k = 512 float4, 2 per thread
        #pragma unroll
        for (int l = 0; l < 2; l++) {
            int f = tid + l * 256;
            int m = f >> 2, kq = f & 3;
            int row = rs[m];
            float4 v = make_float4(0.f, 0.f, 0.f, 0.f);
            if (row >= 0)
                v = *(const float4*)(x + (size_t)row * C_DIM + k0 + kq * 4);
            As[kq * 4 + 0][m] = v.x; As[kq * 4 + 1][m] = v.y;
            As[kq * 4 + 2][m] = v.z; As[kq * 4 + 3][m] = v.w;
        }
        // B tile: 64 rows x 16 k = 256 float4, 1 per thread
        {
            int nn = tid >> 2, kq = tid & 3;
            float4 v = *(const float4*)(wb + (size_t)(n0 + nn) * C_DIM + k0 + kq * 4);
            Bs[kq * 4 + 0][nn] = v.x; Bs[kq * 4 + 1][nn] = v.y;
            Bs[kq * 4 + 2][nn] = v.z; Bs[kq * 4 + 3][nn] = v.w;
        }
        __syncthreads();
        #pragma unroll
        for (int kk = 0; kk < 16; kk++) {
            float a[8], b[4];
            #pragma unroll
            for (int i = 0; i < 8; i++) a[i] = As[kk][ty * 8 + i];
            #pragma unroll
            for (int j = 0; j < 4; j++) b[j] = Bs[kk][tx * 4 + j];
            #pragma unroll
            for (int i = 0; i < 8; i++)
                #pragma unroll
                for (int j = 0; j < 4; j++) acc[i][j] += a[i] * b[j];
        }
        __syncthreads();
    }

    float bb[4];
    #pragma unroll
    for (int j = 0; j < 4; j++) bb[j] = b_up[e * TILE_UP + n0 + tx * 4 + j];

    #pragma unroll
    for (int i = 0; i < 8; i++) {
        int row = rs[ty * 8 + i];
        if (row < 0) continue;
        float4 o;
        o.x = fmaxf(acc[i][0] + bb[0], 0.f);
        o.y = fmaxf(acc[i][1] + bb[1], 0.f);
        o.z = fmaxf(acc[i][2] + bb[2], 0.f);
        o.w = fmaxf(acc[i][3] + bb[3], 0.f);
        *(float4*)(g_hidden + (size_t)row * TILE_UP + n0 + tx * 4) = o;
    }
}

// ---------------------------------------------------------------------------
// Grouped GEMM 2 (down + bias, winner slice only):
//   out[row, e*256+c] = H[row,:] @ W_down[e*256+c, e*1024:(e+1)*1024] + b_down
// grid (4 n-tiles, 128 m-tiles, 4 experts), 256 threads.
// ---------------------------------------------------------------------------
__global__ void __launch_bounds__(256)
gemm_down_kernel(const float* __restrict__ w_down,
                 const float* __restrict__ b_down, float* __restrict__ out) {
    int e = blockIdx.z;
    int cnt = g_cnt[e];
    int m0 = blockIdx.y * 128;
    if (m0 >= cnt) return;
    int n0 = blockIdx.x * 64;

    __shared__ float As[16][128];
    __shared__ float Bs[16][64];
    __shared__ int rs[128];

    int tid = threadIdx.x;
    if (tid < 128) {
        int m = m0 + tid;
        rs[tid] = (m < cnt) ? g_rows[e * N_ROWS + m] : -1;
    }
    __syncthreads();

    int ty = tid >> 4, tx = tid & 15;
    float acc[8][4];
    #pragma unroll
    for (int i = 0; i < 8; i++)
        #pragma unroll
        for (int j = 0; j < 4; j++) acc[i][j] = 0.f;

    const float* wb = w_down + (size_t)e * TILE_DOWN * D_FF + e * TILE_UP;

    for (int k0 = 0; k0 < TILE_UP; k0 += 16) {
        #pragma unroll
        for (int l = 0; l < 2; l++) {
            int f = tid + l * 256;
            int m = f >> 2, kq = f & 3;
            int row = rs[m];
            float4 v = make_float4(0.f, 0.f, 0.f, 0.f);
            if (row >= 0)
                v = *(const float4*)(g_hidden + (size_t)row * TILE_UP + k0 + kq * 4);
            As[kq * 4 + 0][m] = v.x; As[kq * 4 + 1][m] = v.y;
            As[kq * 4 + 2][m] = v.z; As[kq * 4 + 3][m] = v.w;
        }
        {
            int nn = tid >> 2, kq = tid & 3;
            float4 v = *(const float4*)(wb + (size_t)(n0 + nn) * D_FF + k0 + kq * 4);
            Bs[kq * 4 + 0][nn] = v.x; Bs[kq * 4 + 1][nn] = v.y;
            Bs[kq * 4 + 2][nn] = v.z; Bs[kq * 4 + 3][nn] = v.w;
        }
        __syncthreads();
        #pragma unroll
        for (int kk = 0; kk < 16; kk++) {
            float a[8], b[4];
            #pragma unroll
            for (int i = 0; i < 8; i++) a[i] = As[kk][ty * 8 + i];
            #pragma unroll
            for (int j = 0; j < 4; j++) b[j] = Bs[kk][tx * 4 + j];
            #pragma unroll
            for (int i = 0; i < 8; i++)
                #pragma unroll
                for (int j = 0; j < 4; j++) acc[i][j] += a[i] * b[j];
        }
        __syncthreads();
    }

    int colb = e * TILE_DOWN + n0 + tx * 4;
    float bb[4];
    #pragma unroll
    for (int j = 0; j < 4; j++) bb[j] = b_down[colb + j];

    #pragma unroll
    for (int i = 0; i < 8; i++) {
        int row = rs[ty * 8 + i];
        if (row < 0) continue;
        float4 o;
        o.x = acc[i][0] + bb[0];
        o.y = acc[i][1] + bb[1];
        o.z = acc[i][2] + bb[2];
        o.w = acc[i][3] + bb[3];
        *(float4*)(out + (size_t)row * C_DIM + colb) = o;
    }
}

// ---------------------------------------------------------------------------
extern "C" void kernel_launch(void* const* d_in, const int* in_sizes, int n_in,
                              void* d_out, int out_size) {
    const float* x      = (const float*)d_in[0];
    const float* w_up   = (const float*)d_in[1];
    const float* b_up   = (const float*)d_in[2];
    const float* w_down = (const float*)d_in[3];
    const float* b_down = (const float*)d_in[4];
    float* out = (float*)d_out;

    const size_t out_elems = (size_t)N_ROWS * C_DIM;
    int write_gate = (out_size >= (int)(out_elems + (size_t)N_ROWS * NTILES)) ? 1 : 0;

    zero_out_kernel<<<16384, 256>>>((float4*)out);
    sig_kernel<<<dim3(NTILES, C_DIM / 128), 128>>>(w_up);
    route_kernel<<<N_ROWS, 128>>>(x, out + out_elems, write_gate);
    gemm_up_kernel<<<dim3(TILE_UP / 64, N_ROWS / 128, NTILES), 256>>>(x, w_up, b_up);
    gemm_down_kernel<<<dim3(TILE_DOWN / 64, N_ROWS / 128, NTILES), 256>>>(w_down, b_down, out);
}

// round 3
// speedup vs baseline: 2.5903x; 2.5903x over previous
#include <cuda_runtime.h>
#include <cuda_bf16.h>
#include <cstdint>

#define N_ROWS 16384
#define C_DIM  1024
#define NTILES 4

// ---------------- device global scratch (no allocations allowed) ----------------
__device__ float g_sig[NTILES * C_DIM];
__device__ int   g_cnt[NTILES];
__device__ int   g_rows[NTILES * N_ROWS];
__device__ __nv_bfloat16 g_xh[(size_t)N_ROWS * C_DIM];
__device__ __nv_bfloat16 g_xl[(size_t)N_ROWS * C_DIM];
__device__ __nv_bfloat16 g_wuh[(size_t)4096 * 1024];
__device__ __nv_bfloat16 g_wul[(size_t)4096 * 1024];
__device__ __nv_bfloat16 g_wdh[(size_t)1024 * 1024];   // 4 diag blocks [e*256+n][k]
__device__ __nv_bfloat16 g_wdl[(size_t)1024 * 1024];
__device__ __nv_bfloat16 g_hh[(size_t)N_ROWS * 1024];  // hidden hi
__device__ __nv_bfloat16 g_hl[(size_t)N_ROWS * 1024];  // hidden lo

// ---------------- PTX helpers ----------------
static __device__ __forceinline__ uint32_t smem_u32(const void* p) {
    uint32_t a;
    asm("{ .reg .u64 t; cvta.to.shared.u64 t, %1; cvt.u32.u64 %0, t; }" : "=r"(a) : "l"(p));
    return a;
}
static __device__ __forceinline__ void cp16(uint32_t dst, const void* src, int sz) {
    asm volatile("cp.async.cg.shared.global [%0], [%1], 16, %2;" :: "r"(dst), "l"(src), "r"(sz));
}
#define CP_COMMIT() asm volatile("cp.async.commit_group;" ::: "memory")
#define CP_WAIT(n)  asm volatile("cp.async.wait_group %0;" :: "n"(n) : "memory")

static __device__ __forceinline__ void ldsm4(uint32_t* r, uint32_t addr) {
    asm volatile("ldmatrix.sync.aligned.m8n8.x4.shared.b16 {%0,%1,%2,%3}, [%4];"
                 : "=r"(r[0]), "=r"(r[1]), "=r"(r[2]), "=r"(r[3]) : "r"(addr));
}
static __device__ __forceinline__ void mma16816(float* c, const uint32_t* a, const uint32_t* b) {
    asm volatile("mma.sync.aligned.m16n8k16.row.col.f32.bf16.bf16.f32 "
                 "{%0,%1,%2,%3}, {%4,%5,%6,%7}, {%8,%9}, {%0,%1,%2,%3};"
                 : "+f"(c[0]), "+f"(c[1]), "+f"(c[2]), "+f"(c[3])
                 : "r"(a[0]), "r"(a[1]), "r"(a[2]), "r"(a[3]), "r"(b[0]), "r"(b[1]));
}
static __device__ __forceinline__ void split2(float v0, float v1, uint32_t& hi, uint32_t& lo) {
    __nv_bfloat16 h0 = __float2bfloat16(v0), h1 = __float2bfloat16(v1);
    __nv_bfloat16 l0 = __float2bfloat16(v0 - __bfloat162float(h0));
    __nv_bfloat16 l1 = __float2bfloat16(v1 - __bfloat162float(h1));
    __nv_bfloat162 H(h0, h1), L(l0, l1);
    hi = *reinterpret_cast<uint32_t*>(&H);
    lo = *reinterpret_cast<uint32_t*>(&L);
}

// ---------------------------------------------------------------------------
__global__ void zero_out_kernel(float4* __restrict__ out) {
    out[(size_t)blockIdx.x * 256 + threadIdx.x] = make_float4(0.f, 0.f, 0.f, 0.f);
}

// sig[t][c] = sign(sum_r w_up[t*1024+r][c]); also resets counters
__global__ void sig_kernel(const float* __restrict__ w_up) {
    if (blockIdx.x == 0 && blockIdx.y == 0 && threadIdx.x < NTILES)
        g_cnt[threadIdx.x] = 0;
    int t = blockIdx.x;
    int c = blockIdx.y * 128 + threadIdx.x;
    const float* base = w_up + (size_t)t * 1024 * C_DIM + c;
    float s = 0.f;
    #pragma unroll 8
    for (int r = 0; r < 1024; r++) s += base[(size_t)r * C_DIM];
    g_sig[t * C_DIM + c] = (s > 0.f) ? 1.f : ((s < 0.f) ? -1.f : 0.f);
}

// routing (fp32, exact argmax semantics) + bf16 hi/lo split of x
__global__ void route_kernel(const float* __restrict__ x,
                             float* __restrict__ gate_out, int write_gate) {
    __shared__ float red[NTILES][128];
    int n = blockIdx.x;
    int tid = threadIdx.x;
    const float* xr = x + (size_t)n * C_DIM;
    float a0 = 0.f, a1 = 0.f, a2 = 0.f, a3 = 0.f;
    for (int k = tid; k < C_DIM; k += 128) {
        float xv = xr[k];
        a0 += xv * g_sig[k];
        a1 += xv * g_sig[C_DIM + k];
        a2 += xv * g_sig[2 * C_DIM + k];
        a3 += xv * g_sig[3 * C_DIM + k];
        __nv_bfloat16 h = __float2bfloat16(xv);
        g_xh[(size_t)n * C_DIM + k] = h;
        g_xl[(size_t)n * C_DIM + k] = __float2bfloat16(xv - __bfloat162float(h));
    }
    red[0][tid] = a0; red[1][tid] = a1; red[2][tid] = a2; red[3][tid] = a3;
    __syncthreads();
    for (int s = 64; s > 0; s >>= 1) {
        if (tid < s) {
            #pragma unroll
            for (int t = 0; t < NTILES; t++) red[t][tid] += red[t][tid + s];
        }
        __syncthreads();
    }
    if (tid == 0) {
        float best = red[0][0];
        int w = 0;
        #pragma unroll
        for (int t = 1; t < NTILES; t++)
            if (red[t][0] > best) { best = red[t][0]; w = t; }
        int pos = atomicAdd(&g_cnt[w], 1);
        g_rows[w * N_ROWS + pos] = n;
        if (write_gate) {
            #pragma unroll
            for (int t = 0; t < NTILES; t++)
                gate_out[(size_t)n * NTILES + t] = (t == w) ? 1.f : 0.f;
        }
    }
}

__global__ void split_wup_kernel(const float* __restrict__ w) {
    size_t i = (size_t)blockIdx.x * 256 + threadIdx.x;   // 4096*1024 elems
    float v = w[i];
    __nv_bfloat16 h = __float2bfloat16(v);
    g_wuh[i] = h;
    g_wul[i] = __float2bfloat16(v - __bfloat162float(h));
}

__global__ void split_wdown_kernel(const float* __restrict__ w) {
    size_t i = (size_t)blockIdx.x * 256 + threadIdx.x;   // 4*256*1024 elems
    int e = (int)(i >> 18);
    int n = (int)((i >> 10) & 255);
    int k = (int)(i & 1023);
    float v = w[(size_t)(e * 256 + n) * 4096 + e * 1024 + k];
    __nv_bfloat16 h = __float2bfloat16(v);
    g_wdh[i] = h;
    g_wdl[i] = __float2bfloat16(v - __bfloat162float(h));
}

// ---------------------------------------------------------------------------
// Grouped mma.sync GEMM, 3-term bf16 split, fp32 accumulate.
// CTA: 128 gathered rows x 128 cols, K = 1024 in 32 chunks of 32.
// SMEM stage (32KB): Ah | Al | Bh | Bl, each 128 rows x 32 bf16 (64B/row),
// 16B-group XOR swizzle: g' = g ^ ((row>>1)&3)  -> conflict-free cp.async + ldmatrix.
// 8 warps, warp tile 32x64 (warp grid 4m x 2n), m16n8k16 HMMA.
// ---------------------------------------------------------------------------
template<int IS_UP>
__global__ void __launch_bounds__(256, 1)
gemm_kernel(const float* __restrict__ bias, float* __restrict__ outp)
{
    const int e   = blockIdx.z;
    const int cnt = g_cnt[e];
    const int m0  = blockIdx.y * 128;
    if (m0 >= cnt) return;
    const int n0  = blockIdx.x * 128;
    const int tid = threadIdx.x;

    extern __shared__ __align__(1024) uint8_t dynraw[];
    __shared__ int rs[128];
    __shared__ float bsh[128];
    const uint32_t dynu = smem_u32(dynraw);

    const int brow0 = (IS_UP ? e * 1024 : e * 256) + n0;
    const __nv_bfloat16* __restrict__ Ahp = IS_UP ? g_xh  : g_hh;
    const __nv_bfloat16* __restrict__ Alp = IS_UP ? g_xl  : g_hl;
    const __nv_bfloat16* __restrict__ Bhp = IS_UP ? g_wuh : g_wdh;
    const __nv_bfloat16* __restrict__ Blp = IS_UP ? g_wul : g_wdl;

    if (tid < 128) {
        int m = m0 + tid;
        rs[tid]  = (m < cnt) ? g_rows[e * N_ROWS + m] : -1;
        bsh[tid] = bias[brow0 + tid];
    }
    __syncthreads();

    // ---- stage loader: chunk ch (32 k-vals) into slot (32KB) ----
    auto load_stage = [&](int ch, int slot) {
        const uint32_t sb = dynu + slot * 32768;
        #pragma unroll
        for (int l = 0; l < 2; l++) {
            int i = tid * 2 + l;                  // 0..511
            int row = i >> 2, g = i & 3;
            uint32_t off = (uint32_t)row * 64 + (uint32_t)((g ^ ((row >> 1) & 3)) << 4);
            int r = rs[row];
            const size_t ak = (size_t)(r < 0 ? 0 : r) * 1024 + ch * 32 + g * 8;
            int sz = (r < 0) ? 0 : 16;
            cp16(sb + off,         Ahp + ak, sz);
            cp16(sb + 8192 + off,  Alp + ak, sz);
            const size_t bk = (size_t)(brow0 + row) * 1024 + ch * 32 + g * 8;
            cp16(sb + 16384 + off, Bhp + bk, 16);
            cp16(sb + 24576 + off, Blp + bk, 16);
        }
    };

    const int lane = tid & 31, w = tid >> 5;
    const int wm = w >> 1, wn = w & 1;
    const int gid = lane >> 2, qid = lane & 3;

    // precomputed ldmatrix offsets (lane-dependent)
    uint32_t aoff[2][2], boff[4][2];
    #pragma unroll
    for (int mi = 0; mi < 2; mi++)
        #pragma unroll
        for (int s16 = 0; s16 < 2; s16++) {
            int row = wm * 32 + mi * 16 + (lane & 15);
            int g = s16 * 2 + (lane >> 4);
            aoff[mi][s16] = (uint32_t)row * 64 + (uint32_t)((g ^ ((row >> 1) & 3)) << 4);
        }
    #pragma unroll
    for (int nb = 0; nb < 4; nb++)
        #pragma unroll
        for (int s16 = 0; s16 < 2; s16++) {
            int rown = wn * 64 + nb * 16 + (lane & 7) + ((lane >> 4) << 3);
            int g = s16 * 2 + ((lane >> 3) & 1);
            boff[nb][s16] = (uint32_t)rown * 64 + (uint32_t)((g ^ ((rown >> 1) & 3)) << 4);
        }

    float acc[2][8][4];
    #pragma unroll
    for (int mi = 0; mi < 2; mi++)
        #pragma unroll
        for (int nj = 0; nj < 8; nj++)
            #pragma unroll
            for (int q = 0; q < 4; q++) acc[mi][nj][q] = 0.f;

    load_stage(0, 0); CP_COMMIT();
    load_stage(1, 1); CP_COMMIT();

    for (int ch = 0; ch < 32; ch++) {
        CP_WAIT(1);
        __syncthreads();
        const int s = ch % 3;
        const uint32_t sb = dynu + s * 32768;

        #pragma unroll
        for (int s16 = 0; s16 < 2; s16++) {
            uint32_t ah[2][4], al[2][4];
            #pragma unroll
            for (int mi = 0; mi < 2; mi++) {
                ldsm4(ah[mi], sb + aoff[mi][s16]);
                ldsm4(al[mi], sb + 8192 + aoff[mi][s16]);
            }
            uint32_t bh[4][4], bl[4][4];
            #pragma unroll
            for (int nb = 0; nb < 4; nb++) {
                ldsm4(bh[nb], sb + 16384 + boff[nb][s16]);
                ldsm4(bl[nb], sb + 24576 + boff[nb][s16]);
            }
            #pragma unroll
            for (int mi = 0; mi < 2; mi++)
                #pragma unroll
                for (int nj = 0; nj < 8; nj++) {
                    const uint32_t* bph = &bh[nj >> 1][(nj & 1) * 2];
                    const uint32_t* bpl = &bl[nj >> 1][(nj & 1) * 2];
                    mma16816(acc[mi][nj], ah[mi], bph);
                    mma16816(acc[mi][nj], al[mi], bph);
                    mma16816(acc[mi][nj], ah[mi], bpl);
                }
        }

        if (ch + 2 < 32) load_stage(ch + 2, (ch + 2) % 3);
        CP_COMMIT();
        __syncthreads();
    }
    CP_WAIT(0);
    __syncthreads();

    // ---- epilogue through SMEM for coalesced global stores ----
    if (IS_UP) {
        uint32_t* stg = reinterpret_cast<uint32_t*>(dynraw);   // pitch 68 u32; hi @0, lo @8704
        #pragma unroll
        for (int mi = 0; mi < 2; mi++)
            #pragma unroll
            for (int nj = 0; nj < 8; nj++) {
                int col0 = wn * 64 + nj * 8 + 2 * qid;
                int r0 = wm * 32 + mi * 16 + gid;
                float b0 = bsh[col0], b1 = bsh[col0 + 1];
                float v0 = fmaxf(acc[mi][nj][0] + b0, 0.f);
                float v1 = fmaxf(acc[mi][nj][1] + b1, 0.f);
                float v2 = fmaxf(acc[mi][nj][2] + b0, 0.f);
                float v3 = fmaxf(acc[mi][nj][3] + b1, 0.f);
                uint32_t hi0, lo0, hi1, lo1;
                split2(v0, v1, hi0, lo0);
                split2(v2, v3, hi1, lo1);
                int cp = col0 >> 1;
                stg[r0 * 68 + cp]              = hi0;
                stg[(r0 + 8) * 68 + cp]        = hi1;
                stg[8704 + r0 * 68 + cp]       = lo0;
                stg[8704 + (r0 + 8) * 68 + cp] = lo1;
            }
        __syncthreads();
        uint32_t* hh32 = reinterpret_cast<uint32_t*>(g_hh);
        uint32_t* hl32 = reinterpret_cast<uint32_t*>(g_hl);
        for (int i = tid; i < 2048; i += 256) {
            int row = i >> 4, q = i & 15;
            int r = rs[row];
            if (r < 0) continue;
            uint4 vh = *reinterpret_cast<uint4*>(&stg[row * 68 + q * 4]);
            uint4 vl = *reinterpret_cast<uint4*>(&stg[8704 + row * 68 + q * 4]);
            *reinterpret_cast<uint4*>(&hh32[(size_t)r * 512 + (n0 >> 1) + q * 4]) = vh;
            *reinterpret_cast<uint4*>(&hl32[(size_t)r * 512 + (n0 >> 1) + q * 4]) = vl;
        }
    } else {
        float* stg = reinterpret_cast<float*>(dynraw);         // pitch 132 f32
        #pragma unroll
        for (int mi = 0; mi < 2; mi++)
            #pragma unroll
            for (int nj = 0; nj < 8; nj++) {
                int col0 = wn * 64 + nj * 8 + 2 * qid;
                int r0 = wm * 32 + mi * 16 + gid;
                float b0 = bsh[col0], b1 = bsh[col0 + 1];
                stg[r0 * 132 + col0]           = acc[mi][nj][0] + b0;
                stg[r0 * 132 + col0 + 1]       = acc[mi][nj][1] + b1;
                stg[(r0 + 8) * 132 + col0]     = acc[mi][nj][2] + b0;
                stg[(r0 + 8) * 132 + col0 + 1] = acc[mi][nj][3] + b1;
            }
        __syncthreads();
        for (int i = tid; i < 4096; i += 256) {
            int row = i >> 5, q = i & 31;
            int r = rs[row];
            if (r < 0) continue;
            float4 v = *reinterpret_cast<float4*>(&stg[row * 132 + q * 4]);
            *reinterpret_cast<float4*>(&outp[(size_t)r * C_DIM + e * 256 + n0 + q * 4]) = v;
        }
    }
}

// ---------------------------------------------------------------------------
extern "C" void kernel_launch(void* const* d_in, const int* in_sizes, int n_in,
                              void* d_out, int out_size) {
    const float* x      = (const float*)d_in[0];
    const float* w_up   = (const float*)d_in[1];
    const float* b_up   = (const float*)d_in[2];
    const float* w_down = (const float*)d_in[3];
    const float* b_down = (const float*)d_in[4];
    float* out = (float*)d_out;

    const size_t out_elems = (size_t)N_ROWS * C_DIM;
    int write_gate = (out_size >= (int)(out_elems + (size_t)N_ROWS * NTILES)) ? 1 : 0;

    const int SMEM_GEMM = 98304;   // 3 x 32KB stages (epilogue reuses)
    static int attr_done = 0;
    if (!attr_done) {
        cudaFuncSetAttribute(gemm_kernel<1>, cudaFuncAttributeMaxDynamicSharedMemorySize, SMEM_GEMM);
        cudaFuncSetAttribute(gemm_kernel<0>, cudaFuncAttributeMaxDynamicSharedMemorySize, SMEM_GEMM);
        attr_done = 1;
    }

    zero_out_kernel<<<16384, 256>>>((float4*)out);
    sig_kernel<<<dim3(NTILES, C_DIM / 128), 128>>>(w_up);
    route_kernel<<<N_ROWS, 128>>>(x, out + out_elems, write_gate);
    split_wup_kernel<<<16384, 256>>>(w_up);
    split_wdown_kernel<<<4096, 256>>>(w_down);
    gemm_kernel<1><<<dim3(8, 128, NTILES), 256, SMEM_GEMM>>>(b_up, nullptr);
    gemm_kernel<0><<<dim3(2, 128, NTILES), 256, SMEM_GEMM>>>(b_down, out);
}

// round 4
// speedup vs baseline: 4.3833x; 1.6922x over previous
#include <cuda_runtime.h>
#include <cuda_fp16.h>
#include <cstdint>

#define N_ROWS 16384
#define C_DIM  1024
#define NTILES 4

// ---------------- device global scratch (no allocations allowed) ----------------
__device__ float g_part[8 * 4096];        // deterministic partial column sums
__device__ float g_sig[NTILES * C_DIM];
__device__ int   g_cnt[NTILES];
__device__ int   g_rows[NTILES * N_ROWS];
__device__ __half g_xh[(size_t)N_ROWS * C_DIM];
__device__ __half g_xl[(size_t)N_ROWS * C_DIM];
__device__ __half g_wuh[(size_t)4096 * 1024];
__device__ __half g_wdh[(size_t)1024 * 1024];   // 4 diag blocks [e*256+n][k]
__device__ __half g_hh[(size_t)N_ROWS * 1024];  // hidden hi
__device__ __half g_hl[(size_t)N_ROWS * 1024];  // hidden lo

// ---------------- PTX helpers ----------------
static __device__ __forceinline__ uint32_t smem_u32(const void* p) {
    uint32_t a;
    asm("{ .reg .u64 t; cvta.to.shared.u64 t, %1; cvt.u32.u64 %0, t; }" : "=r"(a) : "l"(p));
    return a;
}
static __device__ __forceinline__ void cp16(uint32_t dst, const void* src, int sz) {
    asm volatile("cp.async.cg.shared.global [%0], [%1], 16, %2;" :: "r"(dst), "l"(src), "r"(sz));
}
#define CP_COMMIT() asm volatile("cp.async.commit_group;" ::: "memory")
#define CP_WAIT(n)  asm volatile("cp.async.wait_group %0;" :: "n"(n) : "memory")

static __device__ __forceinline__ void ldsm4(uint32_t* r, uint32_t addr) {
    asm volatile("ldmatrix.sync.aligned.m8n8.x4.shared.b16 {%0,%1,%2,%3}, [%4];"
                 : "=r"(r[0]), "=r"(r[1]), "=r"(r[2]), "=r"(r[3]) : "r"(addr));
}
static __device__ __forceinline__ void mma16816(float* c, const uint32_t* a, const uint32_t* b) {
    asm volatile("mma.sync.aligned.m16n8k16.row.col.f32.f16.f16.f32 "
                 "{%0,%1,%2,%3}, {%4,%5,%6,%7}, {%8,%9}, {%0,%1,%2,%3};"
                 : "+f"(c[0]), "+f"(c[1]), "+f"(c[2]), "+f"(c[3])
                 : "r"(a[0]), "r"(a[1]), "r"(a[2]), "r"(a[3]), "r"(b[0]), "r"(b[1]));
}
static __device__ __forceinline__ void split2h(float v0, float v1, uint32_t& hi, uint32_t& lo) {
    __half h0 = __float2half_rn(v0), h1 = __float2half_rn(v1);
    __half l0 = __float2half_rn(v0 - __half2float(h0));
    __half l1 = __float2half_rn(v1 - __half2float(h1));
    __half2 H = __halves2half2(h0, h1), L = __halves2half2(l0, l1);
    hi = *reinterpret_cast<uint32_t*>(&H);
    lo = *reinterpret_cast<uint32_t*>(&L);
}

// ---------------------------------------------------------------------------
__global__ void zero_out_kernel(float4* __restrict__ out) {
    out[(size_t)blockIdx.x * 256 + threadIdx.x] = make_float4(0.f, 0.f, 0.f, 0.f);
}

// Phase 1: deterministic partial column sums of w_up, 128-row chunks.
// grid 256: t = bx>>6, colblock = (bx>>3)&7, rowchunk = bx&7; 128 threads.
__global__ void sig_sum_kernel(const float* __restrict__ w_up) {
    int bx = blockIdx.x;
    int t  = bx >> 6, cb = (bx >> 3) & 7, rc = bx & 7;
    int c  = cb * 128 + threadIdx.x;
    const float* base = w_up + (size_t)(t * 1024 + rc * 128) * C_DIM + c;
    float s = 0.f;
    #pragma unroll 8
    for (int r = 0; r < 128; r++) s += base[(size_t)r * C_DIM];
    g_part[rc * 4096 + t * C_DIM + c] = s;
}

// Phase 2: fixed-order combine + sign; also resets routing counters.
__global__ void sign_kernel() {
    int i = blockIdx.x * 256 + threadIdx.x;
    if (blockIdx.x == 0 && threadIdx.x < NTILES) g_cnt[threadIdx.x] = 0;
    float s = 0.f;
    #pragma unroll
    for (int rc = 0; rc < 8; rc++) s += g_part[rc * 4096 + i];
    g_sig[i] = (s > 0.f) ? 1.f : ((s < 0.f) ? -1.f : 0.f);
}

// routing (fp32, exact argmax semantics) + fp16 hi/lo split of x
__global__ void route_kernel(const float* __restrict__ x,
                             float* __restrict__ gate_out, int write_gate) {
    __shared__ float red[NTILES][128];
    int n = blockIdx.x;
    int tid = threadIdx.x;
    const float* xr = x + (size_t)n * C_DIM;
    float a0 = 0.f, a1 = 0.f, a2 = 0.f, a3 = 0.f;
    for (int k = tid; k < C_DIM; k += 128) {
        float xv = xr[k];
        a0 += xv * g_sig[k];
        a1 += xv * g_sig[C_DIM + k];
        a2 += xv * g_sig[2 * C_DIM + k];
        a3 += xv * g_sig[3 * C_DIM + k];
        __half h = __float2half_rn(xv);
        g_xh[(size_t)n * C_DIM + k] = h;
        g_xl[(size_t)n * C_DIM + k] = __float2half_rn(xv - __half2float(h));
    }
    red[0][tid] = a0; red[1][tid] = a1; red[2][tid] = a2; red[3][tid] = a3;
    __syncthreads();
    for (int s = 64; s > 0; s >>= 1) {
        if (tid < s) {
            #pragma unroll
            for (int t = 0; t < NTILES; t++) red[t][tid] += red[t][tid + s];
        }
        __syncthreads();
    }
    if (tid == 0) {
        float best = red[0][0];
        int w = 0;
        #pragma unroll
        for (int t = 1; t < NTILES; t++)
            if (red[t][0] > best) { best = red[t][0]; w = t; }
        int pos = atomicAdd(&g_cnt[w], 1);
        g_rows[w * N_ROWS + pos] = n;
        if (write_gate) {
            #pragma unroll
            for (int t = 0; t < NTILES; t++)
                gate_out[(size_t)n * NTILES + t] = (t == w) ? 1.f : 0.f;
        }
    }
}

// w_up -> fp16 (hi only), float4 vectorized: 4M float4
__global__ void split_wup_kernel(const float* __restrict__ w) {
    size_t i = (size_t)blockIdx.x * 256 + threadIdx.x;
    float4 v = reinterpret_cast<const float4*>(w)[i];
    __half2 a = __halves2half2(__float2half_rn(v.x), __float2half_rn(v.y));
    __half2 b = __halves2half2(__float2half_rn(v.z), __float2half_rn(v.w));
    reinterpret_cast<__half2*>(g_wuh)[i * 2]     = a;
    reinterpret_cast<__half2*>(g_wuh)[i * 2 + 1] = b;
}

// w_down diag blocks -> fp16 (hi only), float4 vectorized: 256K float4
__global__ void split_wdown_kernel(const float* __restrict__ w) {
    size_t i = (size_t)blockIdx.x * 256 + threadIdx.x;   // float4 index
    size_t el = i * 4;
    int e = (int)(el >> 18);
    int n = (int)((el >> 10) & 255);
    int k = (int)(el & 1023);
    float4 v = *reinterpret_cast<const float4*>(w + (size_t)(e * 256 + n) * 4096 + e * 1024 + k);
    __half2 a = __halves2half2(__float2half_rn(v.x), __float2half_rn(v.y));
    __half2 b = __halves2half2(__float2half_rn(v.z), __float2half_rn(v.w));
    reinterpret_cast<__half2*>(g_wdh)[i * 2]     = a;
    reinterpret_cast<__half2*>(g_wdh)[i * 2 + 1] = b;
}

// ---------------------------------------------------------------------------
// Grouped mma.sync GEMM, 2-term fp16 split (A = hi+lo, B = hi), fp32 accum.
// CTA: 128 gathered rows x 128 cols, K = 1024 in 32 chunks of 32.
// Stage (24KB): Ah | Al | Bh, each 128 rows x 32 fp16 (64B/row),
// 16B-group XOR swizzle: g' = g ^ ((row>>1)&3). 3-stage cp.async pipeline.
// 8 warps, warp tile 32x64 (grid 4m x 2n), m16n8k16 HMMA.
// ---------------------------------------------------------------------------
template<int IS_UP>
__global__ void __launch_bounds__(256, 2)
gemm_kernel(const float* __restrict__ bias, float* __restrict__ outp)
{
    const int e   = blockIdx.z;
    const int cnt = g_cnt[e];
    const int m0  = blockIdx.y * 128;
    if (m0 >= cnt) return;
    const int n0  = blockIdx.x * 128;
    const int tid = threadIdx.x;

    extern __shared__ __align__(1024) uint8_t dynraw[];
    __shared__ int rs[128];
    __shared__ float bsh[128];
    const uint32_t dynu = smem_u32(dynraw);

    const int brow0 = (IS_UP ? e * 1024 : e * 256) + n0;
    const __half* __restrict__ Ahp = IS_UP ? g_xh  : g_hh;
    const __half* __restrict__ Alp = IS_UP ? g_xl  : g_hl;
    const __half* __restrict__ Bhp = IS_UP ? g_wuh : g_wdh;

    if (tid < 128) {
        int m = m0 + tid;
        rs[tid]  = (m < cnt) ? g_rows[e * N_ROWS + m] : -1;
        bsh[tid] = bias[brow0 + tid];
    }
    __syncthreads();

    // ---- stage loader: chunk ch (32 k-vals) into slot (24KB) ----
    auto load_stage = [&](int ch, int slot) {
        const uint32_t sb = dynu + slot * 24576;
        #pragma unroll
        for (int l = 0; l < 2; l++) {
            int i = tid * 2 + l;                  // 0..511
            int row = i >> 2, g = i & 3;
            uint32_t off = (uint32_t)row * 64 + (uint32_t)((g ^ ((row >> 1) & 3)) << 4);
            int r = rs[row];
            const size_t ak = (size_t)(r < 0 ? 0 : r) * 1024 + ch * 32 + g * 8;
            int sz = (r < 0) ? 0 : 16;
            cp16(sb + off,         Ahp + ak, sz);
            cp16(sb + 8192 + off,  Alp + ak, sz);
            const size_t bk = (size_t)(brow0 + row) * 1024 + ch * 32 + g * 8;
            cp16(sb + 16384 + off, Bhp + bk, 16);
        }
    };

    const int lane = tid & 31, w = tid >> 5;
    const int wm = w >> 1, wn = w & 1;
    const int gid = lane >> 2, qid = lane & 3;

    // precomputed ldmatrix offsets (lane-dependent)
    uint32_t aoff[2][2], boff[4][2];
    #pragma unroll
    for (int mi = 0; mi < 2; mi++)
        #pragma unroll
        for (int s16 = 0; s16 < 2; s16++) {
            int row = wm * 32 + mi * 16 + (lane & 15);
            int g = s16 * 2 + (lane >> 4);
            aoff[mi][s16] = (uint32_t)row * 64 + (uint32_t)((g ^ ((row >> 1) & 3)) << 4);
        }
    #pragma unroll
    for (int nb = 0; nb < 4; nb++)
        #pragma unroll
        for (int s16 = 0; s16 < 2; s16++) {
            int rown = wn * 64 + nb * 16 + (lane & 7) + ((lane >> 4) << 3);
            int g = s16 * 2 + ((lane >> 3) & 1);
            boff[nb][s16] = (uint32_t)rown * 64 + (uint32_t)((g ^ ((rown >> 1) & 3)) << 4);
        }

    float acc[2][8][4];
    #pragma unroll
    for (int mi = 0; mi < 2; mi++)
        #pragma unroll
        for (int nj = 0; nj < 8; nj++)
            #pragma unroll
            for (int q = 0; q < 4; q++) acc[mi][nj][q] = 0.f;

    load_stage(0, 0); CP_COMMIT();
    load_stage(1, 1); CP_COMMIT();

    for (int ch = 0; ch < 32; ch++) {
        CP_WAIT(1);
        __syncthreads();
        const int s = ch % 3;
        const uint32_t sb = dynu + s * 24576;

        #pragma unroll
        for (int s16 = 0; s16 < 2; s16++) {
            uint32_t ah[2][4], al[2][4];
            #pragma unroll
            for (int mi = 0; mi < 2; mi++) {
                ldsm4(ah[mi], sb + aoff[mi][s16]);
                ldsm4(al[mi], sb + 8192 + aoff[mi][s16]);
            }
            uint32_t bh[4][4];
            #pragma unroll
            for (int nb = 0; nb < 4; nb++)
                ldsm4(bh[nb], sb + 16384 + boff[nb][s16]);
            #pragma unroll
            for (int mi = 0; mi < 2; mi++)
                #pragma unroll
                for (int nj = 0; nj < 8; nj++) {
                    const uint32_t* bph = &bh[nj >> 1][(nj & 1) * 2];
                    mma16816(acc[mi][nj], ah[mi], bph);
                    mma16816(acc[mi][nj], al[mi], bph);
                }
        }

        if (ch + 2 < 32) load_stage(ch + 2, (ch + 2) % 3);
        CP_COMMIT();
    }
    CP_WAIT(0);
    __syncthreads();

    // ---- epilogue through SMEM for coalesced global stores ----
    if (IS_UP) {
        uint32_t* stg = reinterpret_cast<uint32_t*>(dynraw);   // pitch 68 u32; hi @0, lo @8704
        #pragma unroll
        for (int mi = 0; mi < 2; mi++)
            #pragma unroll
            for (int nj = 0; nj < 8; nj++) {
                int col0 = wn * 64 + nj * 8 + 2 * qid;
                int r0 = wm * 32 + mi * 16 + gid;
                float b0 = bsh[col0], b1 = bsh[col0 + 1];
                float v0 = fmaxf(acc[mi][nj][0] + b0, 0.f);
                float v1 = fmaxf(acc[mi][nj][1] + b1, 0.f);
                float v2 = fmaxf(acc[mi][nj][2] + b0, 0.f);
                float v3 = fmaxf(acc[mi][nj][3] + b1, 0.f);
                uint32_t hi0, lo0, hi1, lo1;
                split2h(v0, v1, hi0, lo0);
                split2h(v2, v3, hi1, lo1);
                int cp = col0 >> 1;
                stg[r0 * 68 + cp]              = hi0;
                stg[(r0 + 8) * 68 + cp]        = hi1;
                stg[8704 + r0 * 68 + cp]       = lo0;
                stg[8704 + (r0 + 8) * 68 + cp] = lo1;
            }
        __syncthreads();
        uint32_t* hh32 = reinterpret_cast<uint32_t*>(g_hh);
        uint32_t* hl32 = reinterpret_cast<uint32_t*>(g_hl);
        for (int i = tid; i < 2048; i += 256) {
            int row = i >> 4, q = i & 15;
            int r = rs[row];
            if (r < 0) continue;
            uint4 vh = *reinterpret_cast<uint4*>(&stg[row * 68 + q * 4]);
            uint4 vl = *reinterpret_cast<uint4*>(&stg[8704 + row * 68 + q * 4]);
            *reinterpret_cast<uint4*>(&hh32[(size_t)r * 512 + (n0 >> 1) + q * 4]) = vh;
            *reinterpret_cast<uint4*>(&hl32[(size_t)r * 512 + (n0 >> 1) + q * 4]) = vl;
        }
    } else {
        float* stg = reinterpret_cast<float*>(dynraw);         // pitch 132 f32
        #pragma unroll
        for (int mi = 0; mi < 2; mi++)
            #pragma unroll
            for (int nj = 0; nj < 8; nj++) {
                int col0 = wn * 64 + nj * 8 + 2 * qid;
                int r0 = wm * 32 + mi * 16 + gid;
                float b0 = bsh[col0], b1 = bsh[col0 + 1];
                stg[r0 * 132 + col0]           = acc[mi][nj][0] + b0;
                stg[r0 * 132 + col0 + 1]       = acc[mi][nj][1] + b1;
                stg[(r0 + 8) * 132 + col0]     = acc[mi][nj][2] + b0;
                stg[(r0 + 8) * 132 + col0 + 1] = acc[mi][nj][3] + b1;
            }
        __syncthreads();
        for (int i = tid; i < 4096; i += 256) {
            int row = i >> 5, q = i & 31;
            int r = rs[row];
            if (r < 0) continue;
            float4 v = *reinterpret_cast<float4*>(&stg[row * 132 + q * 4]);
            *reinterpret_cast<float4*>(&outp[(size_t)r * C_DIM + e * 256 + n0 + q * 4]) = v;
        }
    }
}

// ---------------------------------------------------------------------------
extern "C" void kernel_launch(void* const* d_in, const int* in_sizes, int n_in,
                              void* d_out, int out_size) {
    const float* x      = (const float*)d_in[0];
    const float* w_up   = (const float*)d_in[1];
    const float* b_up   = (const float*)d_in[2];
    const float* w_down = (const float*)d_in[3];
    const float* b_down = (const float*)d_in[4];
    float* out = (float*)d_out;

    const size_t out_elems = (size_t)N_ROWS * C_DIM;
    int write_gate = (out_size >= (int)(out_elems + (size_t)N_ROWS * NTILES)) ? 1 : 0;

    const int SMEM_GEMM = 73728;   // 3 x 24KB stages (epilogue reuses)
    static int attr_done = 0;
    if (!attr_done) {
        cudaFuncSetAttribute(gemm_kernel<1>, cudaFuncAttributeMaxDynamicSharedMemorySize, SMEM_GEMM);
        cudaFuncSetAttribute(gemm_kernel<0>, cudaFuncAttributeMaxDynamicSharedMemorySize, SMEM_GEMM);
        attr_done = 1;
    }

    zero_out_kernel<<<16384, 256>>>((float4*)out);
    sig_sum_kernel<<<256, 128>>>(w_up);
    sign_kernel<<<16, 256>>>();
    route_kernel<<<N_ROWS, 128>>>(x, out + out_elems, write_gate);
    split_wup_kernel<<<16384, 256>>>(w_up);
    split_wdown_kernel<<<1024, 256>>>(w_down);
    gemm_kernel<1><<<dim3(8, 128, NTILES), 256, SMEM_GEMM>>>(b_up, nullptr);
    gemm_kernel<0><<<dim3(2, 128, NTILES), 256, SMEM_GEMM>>>(b_down, out);
}

// round 5
// speedup vs baseline: 4.5069x; 1.0282x over previous
#include <cuda_runtime.h>
#include <cuda_fp16.h>
#include <cstdint>

#define N_ROWS 16384
#define C_DIM  1024
#define NTILES 4

// ---------------- device global scratch (no allocations allowed) ----------------
__device__ float g_part[32 * 4096];       // deterministic partial column sums
__device__ float g_sig[NTILES * C_DIM];
__device__ int   g_cnt[NTILES];
__device__ int   g_rows[NTILES * N_ROWS];
__device__ __half g_xh[(size_t)N_ROWS * C_DIM];
__device__ __half g_xl[(size_t)N_ROWS * C_DIM];
__device__ __half g_wuh[(size_t)4096 * 1024];
__device__ __half g_wdh[(size_t)1024 * 1024];   // 4 diag blocks [e*256+n][k]
__device__ __half g_hh[(size_t)N_ROWS * 1024];  // hidden hi
__device__ __half g_hl[(size_t)N_ROWS * 1024];  // hidden lo

// ---------------- PTX helpers ----------------
static __device__ __forceinline__ uint32_t smem_u32(const void* p) {
    uint32_t a;
    asm("{ .reg .u64 t; cvta.to.shared.u64 t, %1; cvt.u32.u64 %0, t; }" : "=r"(a) : "l"(p));
    return a;
}
static __device__ __forceinline__ void cp16(uint32_t dst, const void* src, int sz) {
    asm volatile("cp.async.cg.shared.global [%0], [%1], 16, %2;" :: "r"(dst), "l"(src), "r"(sz));
}
#define CP_COMMIT() asm volatile("cp.async.commit_group;" ::: "memory")
#define CP_WAIT(n)  asm volatile("cp.async.wait_group %0;" :: "n"(n) : "memory")

static __device__ __forceinline__ void ldsm4(uint32_t* r, uint32_t addr) {
    asm volatile("ldmatrix.sync.aligned.m8n8.x4.shared.b16 {%0,%1,%2,%3}, [%4];"
                 : "=r"(r[0]), "=r"(r[1]), "=r"(r[2]), "=r"(r[3]) : "r"(addr));
}
static __device__ __forceinline__ void mma16816(float* c, const uint32_t* a, const uint32_t* b) {
    asm volatile("mma.sync.aligned.m16n8k16.row.col.f32.f16.f16.f32 "
                 "{%0,%1,%2,%3}, {%4,%5,%6,%7}, {%8,%9}, {%0,%1,%2,%3};"
                 : "+f"(c[0]), "+f"(c[1]), "+f"(c[2]), "+f"(c[3])
                 : "r"(a[0]), "r"(a[1]), "r"(a[2]), "r"(a[3]), "r"(b[0]), "r"(b[1]));
}

// ---------------------------------------------------------------------------
// Phase 1: partial column sums of w_up (32-row chunks) FUSED with fp16 convert.
// grid 1024: t = bx>>8, cb = (bx>>5)&7, rc = bx&31; 128 threads.
__global__ void sig_sum_kernel(const float* __restrict__ w_up) {
    int bx = blockIdx.x;
    int t  = bx >> 8, cb = (bx >> 5) & 7, rc = bx & 31;
    int c  = cb * 128 + threadIdx.x;
    int row0 = t * 1024 + rc * 32;
    const float* base = w_up + (size_t)row0 * C_DIM + c;
    float s = 0.f;
    #pragma unroll 8
    for (int r = 0; r < 32; r++) {
        float v = base[(size_t)r * C_DIM];
        s += v;
        g_wuh[(size_t)(row0 + r) * C_DIM + c] = __float2half_rn(v);
    }
    g_part[rc * 4096 + t * C_DIM + c] = s;
}

// Phase 2: fixed-order combine + sign; also resets routing counters.
__global__ void sign_kernel() {
    int i = blockIdx.x * 256 + threadIdx.x;
    if (blockIdx.x == 0 && threadIdx.x < NTILES) g_cnt[threadIdx.x] = 0;
    float s = 0.f;
    #pragma unroll
    for (int rc = 0; rc < 32; rc++) s += g_part[rc * 4096 + i];
    g_sig[i] = (s > 0.f) ? 1.f : ((s < 0.f) ? -1.f : 0.f);
}

// routing (fp32, exact argmax semantics) + fp16 hi/lo split of x, vectorized.
// 128 threads per row; each thread: 8 consecutive elems (2 float4).
__global__ void route_kernel(const float* __restrict__ x,
                             float* __restrict__ gate_out, int write_gate) {
    __shared__ float red[NTILES][128];
    int n = blockIdx.x;
    int tid = threadIdx.x;
    const float4* xr = reinterpret_cast<const float4*>(x + (size_t)n * C_DIM);
    float a[NTILES] = {0.f, 0.f, 0.f, 0.f};
    __half hh[8], hl[8];
    #pragma unroll
    for (int q = 0; q < 2; q++) {
        int k4 = tid * 2 + q;              // float4 index 0..255
        float4 v = xr[k4];
        float vv[4] = {v.x, v.y, v.z, v.w};
        #pragma unroll
        for (int t = 0; t < NTILES; t++) {
            const float4 sg = reinterpret_cast<const float4*>(g_sig + t * C_DIM)[k4];
            a[t] += v.x * sg.x + v.y * sg.y + v.z * sg.z + v.w * sg.w;
        }
        #pragma unroll
        for (int j = 0; j < 4; j++) {
            __half h = __float2half_rn(vv[j]);
            hh[q * 4 + j] = h;
            hl[q * 4 + j] = __float2half_rn(vv[j] - __half2float(h));
        }
    }
    *reinterpret_cast<uint4*>(g_xh + (size_t)n * C_DIM + tid * 8) = *reinterpret_cast<uint4*>(hh);
    *reinterpret_cast<uint4*>(g_xl + (size_t)n * C_DIM + tid * 8) = *reinterpret_cast<uint4*>(hl);

    #pragma unroll
    for (int t = 0; t < NTILES; t++) red[t][tid] = a[t];
    __syncthreads();
    for (int s = 64; s > 0; s >>= 1) {
        if (tid < s) {
            #pragma unroll
            for (int t = 0; t < NTILES; t++) red[t][tid] += red[t][tid + s];
        }
        __syncthreads();
    }
    if (tid == 0) {
        float best = red[0][0];
        int w = 0;
        #pragma unroll
        for (int t = 1; t < NTILES; t++)
            if (red[t][0] > best) { best = red[t][0]; w = t; }
        int pos = atomicAdd(&g_cnt[w], 1);
        g_rows[w * N_ROWS + pos] = n;
        if (write_gate) {
            #pragma unroll
            for (int t = 0; t < NTILES; t++)
                gate_out[(size_t)n * NTILES + t] = (t == w) ? 1.f : 0.f;
        }
    }
}

// w_down diag blocks -> fp16, float4 vectorized: 256K float4
__global__ void split_wdown_kernel(const float* __restrict__ w) {
    size_t i = (size_t)blockIdx.x * 256 + threadIdx.x;   // float4 index
    size_t el = i * 4;
    int e = (int)(el >> 18);
    int n = (int)((el >> 10) & 255);
    int k = (int)(el & 1023);
    float4 v = *reinterpret_cast<const float4*>(w + (size_t)(e * 256 + n) * 4096 + e * 1024 + k);
    __half2 a = __halves2half2(__float2half_rn(v.x), __float2half_rn(v.y));
    __half2 b = __halves2half2(__float2half_rn(v.z), __float2half_rn(v.w));
    reinterpret_cast<__half2*>(g_wdh)[i * 2]     = a;
    reinterpret_cast<__half2*>(g_wdh)[i * 2 + 1] = b;
}

// ---------------------------------------------------------------------------
// Grouped mma.sync GEMM, 2-term fp16 split (A = hi+lo, B = hi), fp32 accum.
// CTA: 128 gathered rows x 256 cols, K = 1024 in 32 chunks of 32.
// Stage (32KB): Ah(8K) | Al(8K) | Bh(16K); rows x 32 fp16 (64B/row),
// 16B-group XOR swizzle. 3-stage cp.async pipeline; 512 thr, 16 warps 4m x 4n.
// IS_UP=0 also writes the zero blocks of out (full 1024 cols per routed row).
// ---------------------------------------------------------------------------
template<int IS_UP>
__global__ void __launch_bounds__(512, 1)
gemm_kernel(const float* __restrict__ bias, float* __restrict__ outp)
{
    const int e   = blockIdx.z;
    const int cnt = g_cnt[e];
    const int m0  = blockIdx.y * 128;
    if (m0 >= cnt) return;
    const int n0  = blockIdx.x * 256;
    const int tid = threadIdx.x;

    extern __shared__ __align__(1024) uint8_t dynraw[];
    __shared__ int rs[128];
    __shared__ float bsh[256];
    const uint32_t dynu = smem_u32(dynraw);

    const int brow0 = (IS_UP ? e * 1024 : e * 256) + n0;
    const __half* __restrict__ Ahp = IS_UP ? g_xh  : g_hh;
    const __half* __restrict__ Alp = IS_UP ? g_xl  : g_hl;
    const __half* __restrict__ Bhp = IS_UP ? g_wuh : g_wdh;

    if (tid < 128) {
        int m = m0 + tid;
        rs[tid] = (m < cnt) ? g_rows[e * N_ROWS + m] : -1;
    }
    if (tid < 256) bsh[tid] = bias[brow0 + tid];
    __syncthreads();

    // ---- stage loader: chunk ch (32 k-vals) into slot (32KB) ----
    auto load_stage = [&](int ch, int slot) {
        const uint32_t sb = dynu + slot * 32768;
        {   // A: 128 rows, 4 groups -> 512 cp16 each for hi/lo
            int row = tid >> 2, g = tid & 3;
            uint32_t off = (uint32_t)row * 64 + (uint32_t)((g ^ ((row >> 1) & 3)) << 4);
            int r = rs[row];
            const size_t ak = (size_t)(r < 0 ? 0 : r) * 1024 + ch * 32 + g * 8;
            int sz = (r < 0) ? 0 : 16;
            cp16(sb + off,        Ahp + ak, sz);
            cp16(sb + 8192 + off, Alp + ak, sz);
        }
        #pragma unroll
        for (int l = 0; l < 2; l++) {   // B: 256 rows -> 1024 cp16
            int j = tid * 2 + l;
            int row = j >> 2, g = j & 3;
            uint32_t off = (uint32_t)row * 64 + (uint32_t)((g ^ ((row >> 1) & 3)) << 4);
            const size_t bk = (size_t)(brow0 + row) * 1024 + ch * 32 + g * 8;
            cp16(sb + 16384 + off, Bhp + bk, 16);
        }
    };

    const int lane = tid & 31, w = tid >> 5;
    const int wm = w >> 2, wn = w & 3;
    const int gid = lane >> 2, qid = lane & 3;

    // precomputed ldmatrix offsets (lane-dependent)
    uint32_t aoff[2][2], boff[4][2];
    #pragma unroll
    for (int mi = 0; mi < 2; mi++)
        #pragma unroll
        for (int s16 = 0; s16 < 2; s16++) {
            int row = wm * 32 + mi * 16 + (lane & 15);
            int g = s16 * 2 + (lane >> 4);
            aoff[mi][s16] = (uint32_t)row * 64 + (uint32_t)((g ^ ((row >> 1) & 3)) << 4);
        }
    #pragma unroll
    for (int nb = 0; nb < 4; nb++)
        #pragma unroll
        for (int s16 = 0; s16 < 2; s16++) {
            int rown = wn * 64 + nb * 16 + (lane & 7) + ((lane >> 4) << 3);
            int g = s16 * 2 + ((lane >> 3) & 1);
            boff[nb][s16] = (uint32_t)rown * 64 + (uint32_t)((g ^ ((rown >> 1) & 3)) << 4);
        }

    float acc[2][8][4];
    #pragma unroll
    for (int mi = 0; mi < 2; mi++)
        #pragma unroll
        for (int nj = 0; nj < 8; nj++)
            #pragma unroll
            for (int q = 0; q < 4; q++) acc[mi][nj][q] = 0.f;

    load_stage(0, 0); CP_COMMIT();
    load_stage(1, 1); CP_COMMIT();

    for (int ch = 0; ch < 32; ch++) {
        CP_WAIT(1);
        __syncthreads();
        const int s = ch % 3;
        const uint32_t sb = dynu + s * 32768;

        #pragma unroll
        for (int s16 = 0; s16 < 2; s16++) {
            uint32_t ah[2][4], al[2][4];
            #pragma unroll
            for (int mi = 0; mi < 2; mi++) {
                ldsm4(ah[mi], sb + aoff[mi][s16]);
                ldsm4(al[mi], sb + 8192 + aoff[mi][s16]);
            }
            uint32_t bh[4][4];
            #pragma unroll
            for (int nb = 0; nb < 4; nb++)
                ldsm4(bh[nb], sb + 16384 + boff[nb][s16]);
            #pragma unroll
            for (int mi = 0; mi < 2; mi++)
                #pragma unroll
                for (int nj = 0; nj < 8; nj++) {
                    const uint32_t* bph = &bh[nj >> 1][(nj & 1) * 2];
                    mma16816(acc[mi][nj], ah[mi], bph);
                    mma16816(acc[mi][nj], al[mi], bph);
                }
        }

        if (ch + 2 < 32) load_stage(ch + 2, (ch + 2) % 3);
        CP_COMMIT();
    }
    CP_WAIT(0);
    __syncthreads();

    // ---- epilogue through SMEM for coalesced global stores ----
    if (IS_UP) {
        // two passes: hi then lo. stg pitch 132 u32, 128 rows (67.6KB).
        uint32_t* stg = reinterpret_cast<uint32_t*>(dynraw);
        #pragma unroll
        for (int pass = 0; pass < 2; pass++) {
            #pragma unroll
            for (int mi = 0; mi < 2; mi++)
                #pragma unroll
                for (int nj = 0; nj < 8; nj++) {
                    int col0 = wn * 64 + nj * 8 + 2 * qid;
                    int r0 = wm * 32 + mi * 16 + gid;
                    float b0 = bsh[col0], b1 = bsh[col0 + 1];
                    float v0 = fmaxf(acc[mi][nj][0] + b0, 0.f);
                    float v1 = fmaxf(acc[mi][nj][1] + b1, 0.f);
                    float v2 = fmaxf(acc[mi][nj][2] + b0, 0.f);
                    float v3 = fmaxf(acc[mi][nj][3] + b1, 0.f);
                    __half h0 = __float2half_rn(v0), h1 = __float2half_rn(v1);
                    __half h2 = __float2half_rn(v2), h3 = __float2half_rn(v3);
                    __half2 p01, p23;
                    if (pass == 0) {
                        p01 = __halves2half2(h0, h1);
                        p23 = __halves2half2(h2, h3);
                    } else {
                        p01 = __halves2half2(__float2half_rn(v0 - __half2float(h0)),
                                             __float2half_rn(v1 - __half2float(h1)));
                        p23 = __halves2half2(__float2half_rn(v2 - __half2float(h2)),
                                             __float2half_rn(v3 - __half2float(h3)));
                    }
                    int cp = col0 >> 1;
                    stg[r0 * 132 + cp]       = *reinterpret_cast<uint32_t*>(&p01);
                    stg[(r0 + 8) * 132 + cp] = *reinterpret_cast<uint32_t*>(&p23);
                }
            __syncthreads();
            uint32_t* dst32 = reinterpret_cast<uint32_t*>(pass ? g_hl : g_hh);
            for (int i = tid; i < 4096; i += 512) {
                int row = i >> 5, q = i & 31;
                int r = rs[row];
                if (r < 0) continue;
                uint4 v = *reinterpret_cast<uint4*>(&stg[row * 132 + q * 4]);
                *reinterpret_cast<uint4*>(&dst32[(size_t)r * 512 + (n0 >> 1) + q * 4]) = v;
            }
            __syncthreads();
        }
    } else {
        // two 128-col passes (fp32), then zero-fill the other 768 cols.
        float* stgf = reinterpret_cast<float*>(dynraw);
        #pragma unroll
        for (int pass = 0; pass < 2; pass++) {
            if ((wn >> 1) == pass) {
                #pragma unroll
                for (int mi = 0; mi < 2; mi++)
                    #pragma unroll
                    for (int nj = 0; nj < 8; nj++) {
                        int col0 = wn * 64 + nj * 8 + 2 * qid;
                        int r0 = wm * 32 + mi * 16 + gid;
                        float b0 = bsh[col0], b1 = bsh[col0 + 1];
                        int cl = col0 - pass * 128;
                        stgf[r0 * 132 + cl]           = acc[mi][nj][0] + b0;
                        stgf[r0 * 132 + cl + 1]       = acc[mi][nj][1] + b1;
                        stgf[(r0 + 8) * 132 + cl]     = acc[mi][nj][2] + b0;
                        stgf[(r0 + 8) * 132 + cl + 1] = acc[mi][nj][3] + b1;
                    }
            }
            __syncthreads();
            for (int i = tid; i < 4096; i += 512) {
                int row = i >> 5, q = i & 31;
                int r = rs[row];
                if (r < 0) continue;
                float4 v = *reinterpret_cast<float4*>(&stgf[row * 132 + q * 4]);
                *reinterpret_cast<float4*>(&outp[(size_t)r * C_DIM + e * 256 + pass * 128 + q * 4]) = v;
            }
            __syncthreads();
        }
        const float4 z4 = make_float4(0.f, 0.f, 0.f, 0.f);
        for (int i = tid; i < 128 * 192; i += 512) {
            int row = i / 192, j = i - row * 192;
            int r = rs[row];
            if (r < 0) continue;
            int zcol = j * 4;
            if (zcol >= e * 256) zcol += 256;
            *reinterpret_cast<float4*>(&outp[(size_t)r * C_DIM + zcol]) = z4;
        }
    }
}

// ---------------------------------------------------------------------------
extern "C" void kernel_launch(void* const* d_in, const int* in_sizes, int n_in,
                              void* d_out, int out_size) {
    const float* x      = (const float*)d_in[0];
    const float* w_up   = (const float*)d_in[1];
    const float* b_up   = (const float*)d_in[2];
    const float* w_down = (const float*)d_in[3];
    const float* b_down = (const float*)d_in[4];
    float* out = (float*)d_out;

    const size_t out_elems = (size_t)N_ROWS * C_DIM;
    int write_gate = (out_size >= (int)(out_elems + (size_t)N_ROWS * NTILES)) ? 1 : 0;

    const int SMEM_GEMM = 98304;   // 3 x 32KB stages (epilogue reuses)
    static int attr_done = 0;
    if (!attr_done) {
        cudaFuncSetAttribute(gemm_kernel<1>, cudaFuncAttributeMaxDynamicSharedMemorySize, SMEM_GEMM);
        cudaFuncSetAttribute(gemm_kernel<0>, cudaFuncAttributeMaxDynamicSharedMemorySize, SMEM_GEMM);
        attr_done = 1;
    }

    sig_sum_kernel<<<1024, 128>>>(w_up);
    sign_kernel<<<16, 256>>>();
    route_kernel<<<N_ROWS, 128>>>(x, out + out_elems, write_gate);
    split_wdown_kernel<<<1024, 256>>>(w_down);
    gemm_kernel<1><<<dim3(4, 128, NTILES), 512, SMEM_GEMM>>>(b_up, nullptr);
    gemm_kernel<0><<<dim3(1, 128, NTILES), 512, SMEM_GEMM>>>(b_down, out);
}

// round 6
// speedup vs baseline: 4.8798x; 1.0827x over previous
#include <cuda_runtime.h>
#include <cuda_fp16.h>
#include <cstdint>

#define N_ROWS 16384
#define C_DIM  1024
#define NTILES 4

// ---------------- device global scratch (no allocations allowed) ----------------
__device__ float g_part[32 * 4096];       // deterministic partial column sums
__device__ float g_sig[NTILES * C_DIM];
__device__ int   g_cnt[NTILES];
__device__ int   g_rows[NTILES * N_ROWS];
__device__ __half g_xh[(size_t)N_ROWS * C_DIM];
__device__ __half g_xl[(size_t)N_ROWS * C_DIM];
__device__ __half g_wuh[(size_t)4096 * 1024];
__device__ __half g_wdh[(size_t)1024 * 1024];   // 4 diag blocks [e*256+n][k]
__device__ __half g_hh[(size_t)N_ROWS * 1024];  // hidden (fp16)

// ---------------- PTX helpers ----------------
static __device__ __forceinline__ uint32_t smem_u32(const void* p) {
    uint32_t a;
    asm("{ .reg .u64 t; cvta.to.shared.u64 t, %1; cvt.u32.u64 %0, t; }" : "=r"(a) : "l"(p));
    return a;
}
static __device__ __forceinline__ void cp16(uint32_t dst, const void* src, int sz) {
    asm volatile("cp.async.cg.shared.global [%0], [%1], 16, %2;" :: "r"(dst), "l"(src), "r"(sz));
}
#define CP_COMMIT() asm volatile("cp.async.commit_group;" ::: "memory")
#define CP_WAIT(n)  asm volatile("cp.async.wait_group %0;" :: "n"(n) : "memory")

static __device__ __forceinline__ void ldsm4(uint32_t* r, uint32_t addr) {
    asm volatile("ldmatrix.sync.aligned.m8n8.x4.shared.b16 {%0,%1,%2,%3}, [%4];"
                 : "=r"(r[0]), "=r"(r[1]), "=r"(r[2]), "=r"(r[3]) : "r"(addr));
}
static __device__ __forceinline__ void mma16816(float* c, const uint32_t* a, const uint32_t* b) {
    asm volatile("mma.sync.aligned.m16n8k16.row.col.f32.f16.f16.f32 "
                 "{%0,%1,%2,%3}, {%4,%5,%6,%7}, {%8,%9}, {%0,%1,%2,%3};"
                 : "+f"(c[0]), "+f"(c[1]), "+f"(c[2]), "+f"(c[3])
                 : "r"(a[0]), "r"(a[1]), "r"(a[2]), "r"(a[3]), "r"(b[0]), "r"(b[1]));
}

// 128B-row swizzle (Swizzle<3,4,3>): 16B-group g' = g ^ (row & 7)
static __device__ __forceinline__ uint32_t swz(int row, int g) {
    return (uint32_t)row * 128 + (uint32_t)((g ^ (row & 7)) << 4);
}

// ---------------------------------------------------------------------------
// Phase 1: partial column sums of w_up (32-row chunks) FUSED with fp16 convert.
__global__ void sig_sum_kernel(const float* __restrict__ w_up) {
    int bx = blockIdx.x;
    int t  = bx >> 8, cb = (bx >> 5) & 7, rc = bx & 31;
    int c  = cb * 128 + threadIdx.x;
    int row0 = t * 1024 + rc * 32;
    const float* base = w_up + (size_t)row0 * C_DIM + c;
    float s = 0.f;
    #pragma unroll 8
    for (int r = 0; r < 32; r++) {
        float v = base[(size_t)r * C_DIM];
        s += v;
        g_wuh[(size_t)(row0 + r) * C_DIM + c] = __float2half_rn(v);
    }
    g_part[rc * 4096 + t * C_DIM + c] = s;
}

// Phase 2: fixed-order combine + sign; also resets routing counters.
__global__ void sign_kernel() {
    int i = blockIdx.x * 256 + threadIdx.x;
    if (blockIdx.x == 0 && threadIdx.x < NTILES) g_cnt[threadIdx.x] = 0;
    float s = 0.f;
    #pragma unroll
    for (int rc = 0; rc < 32; rc++) s += g_part[rc * 4096 + i];
    g_sig[i] = (s > 0.f) ? 1.f : ((s < 0.f) ? -1.f : 0.f);
}

// routing (fp32, exact argmax semantics) + fp16 hi/lo split of x, vectorized.
__global__ void route_kernel(const float* __restrict__ x,
                             float* __restrict__ gate_out, int write_gate) {
    __shared__ float red[NTILES][128];
    int n = blockIdx.x;
    int tid = threadIdx.x;
    const float4* xr = reinterpret_cast<const float4*>(x + (size_t)n * C_DIM);
    float a[NTILES] = {0.f, 0.f, 0.f, 0.f};
    __half hh[8], hl[8];
    #pragma unroll
    for (int q = 0; q < 2; q++) {
        int k4 = tid * 2 + q;              // float4 index 0..255
        float4 v = xr[k4];
        float vv[4] = {v.x, v.y, v.z, v.w};
        #pragma unroll
        for (int t = 0; t < NTILES; t++) {
            const float4 sg = reinterpret_cast<const float4*>(g_sig + t * C_DIM)[k4];
            a[t] += v.x * sg.x + v.y * sg.y + v.z * sg.z + v.w * sg.w;
        }
        #pragma unroll
        for (int j = 0; j < 4; j++) {
            __half h = __float2half_rn(vv[j]);
            hh[q * 4 + j] = h;
            hl[q * 4 + j] = __float2half_rn(vv[j] - __half2float(h));
        }
    }
    *reinterpret_cast<uint4*>(g_xh + (size_t)n * C_DIM + tid * 8) = *reinterpret_cast<uint4*>(hh);
    *reinterpret_cast<uint4*>(g_xl + (size_t)n * C_DIM + tid * 8) = *reinterpret_cast<uint4*>(hl);

    #pragma unroll
    for (int t = 0; t < NTILES; t++) red[t][tid] = a[t];
    __syncthreads();
    for (int s = 64; s > 0; s >>= 1) {
        if (tid < s) {
            #pragma unroll
            for (int t = 0; t < NTILES; t++) red[t][tid] += red[t][tid + s];
        }
        __syncthreads();
    }
    if (tid == 0) {
        float best = red[0][0];
        int w = 0;
        #pragma unroll
        for (int t = 1; t < NTILES; t++)
            if (red[t][0] > best) { best = red[t][0]; w = t; }
        int pos = atomicAdd(&g_cnt[w], 1);
        g_rows[w * N_ROWS + pos] = n;
        if (write_gate) {
            #pragma unroll
            for (int t = 0; t < NTILES; t++)
                gate_out[(size_t)n * NTILES + t] = (t == w) ? 1.f : 0.f;
        }
    }
}

// w_down diag blocks -> fp16, float4 vectorized: 256K float4
__global__ void split_wdown_kernel(const float* __restrict__ w) {
    size_t i = (size_t)blockIdx.x * 256 + threadIdx.x;   // float4 index
    size_t el = i * 4;
    int e = (int)(el >> 18);
    int n = (int)((el >> 10) & 255);
    int k = (int)(el & 1023);
    float4 v = *reinterpret_cast<const float4*>(w + (size_t)(e * 256 + n) * 4096 + e * 1024 + k);
    __half2 a = __halves2half2(__float2half_rn(v.x), __float2half_rn(v.y));
    __half2 b = __halves2half2(__float2half_rn(v.z), __float2half_rn(v.w));
    reinterpret_cast<__half2*>(g_wdh)[i * 2]     = a;
    reinterpret_cast<__half2*>(g_wdh)[i * 2 + 1] = b;
}

// ---------------------------------------------------------------------------
// Grouped mma.sync GEMM. fp32 accum. CTA: 128 gathered rows x 256 cols,
// K = 1024 in 16 chunks of 64. 128B rows, Swizzle<3,4,3>, 3-stage cp.async.
// 512 thr, 16 warps 4m x 4n, warp tile 32x64.
// IS_UP=1: A = xh + xl (2-term), B = wuh; epilogue bias+ReLU -> g_hh (fp16).
// IS_UP=0: A = hh (1-term),      B = wdh; epilogue bias -> out slice + zeros.
// ---------------------------------------------------------------------------
template<int IS_UP>
__global__ void __launch_bounds__(512, 1)
gemm_kernel(const float* __restrict__ bias, float* __restrict__ outp)
{
    const int e   = blockIdx.z;
    const int cnt = g_cnt[e];
    const int m0  = blockIdx.y * 128;
    if (m0 >= cnt) return;
    const int n0  = blockIdx.x * 256;
    const int tid = threadIdx.x;

    constexpr uint32_t SSZ  = IS_UP ? 65536 : 49152;   // stage bytes
    constexpr uint32_t BOFF = IS_UP ? 32768 : 16384;   // B offset in stage

    extern __shared__ __align__(1024) uint8_t dynraw[];
    __shared__ int rs[128];
    __shared__ float bsh[256];
    const uint32_t dynu = smem_u32(dynraw);

    const int brow0 = (IS_UP ? e * 1024 : e * 256) + n0;
    const __half* __restrict__ Ahp = IS_UP ? g_xh : g_hh;
    const __half* __restrict__ Bhp = IS_UP ? g_wuh : g_wdh;

    if (tid < 128) {
        int m = m0 + tid;
        rs[tid] = (m < cnt) ? g_rows[e * N_ROWS + m] : -1;
    }
    if (tid < 256) bsh[tid] = bias[brow0 + tid];
    __syncthreads();

    // ---- stage loader: chunk ch (64 k-vals) into slot ----
    auto load_stage = [&](int ch, int slot) {
        const uint32_t sb = dynu + slot * SSZ;
        #pragma unroll
        for (int l = 0; l < 2; l++) {        // A: 128 rows x 8 groups = 1024 sites
            int i = tid * 2 + l;
            int row = i >> 3, g = i & 7;
            uint32_t off = swz(row, g);
            int r = rs[row];
            const size_t ak = (size_t)(r < 0 ? 0 : r) * 1024 + ch * 64 + g * 8;
            int sz = (r < 0) ? 0 : 16;
            cp16(sb + off, Ahp + ak, sz);
            if (IS_UP) cp16(sb + 16384 + off, g_xl + ak, sz);
        }
        #pragma unroll
        for (int l = 0; l < 4; l++) {        // B: 256 rows x 8 groups = 2048 sites
            int j = tid * 4 + l;
            int row = j >> 3, g = j & 7;
            uint32_t off = swz(row, g);
            const size_t bk = (size_t)(brow0 + row) * 1024 + ch * 64 + g * 8;
            cp16(sb + BOFF + off, Bhp + bk, 16);
        }
    };

    const int lane = tid & 31, w = tid >> 5;
    const int wm = w >> 2, wn = w & 3;
    const int gid = lane >> 2, qid = lane & 3;

    // precomputed ldmatrix offsets (lane-dependent), 4 k16-sections per chunk
    uint32_t aoff[2][4], boff[4][4];
    #pragma unroll
    for (int mi = 0; mi < 2; mi++)
        #pragma unroll
        for (int s16 = 0; s16 < 4; s16++) {
            int row = wm * 32 + mi * 16 + (lane & 15);
            aoff[mi][s16] = swz(row, s16 * 2 + (lane >> 4));
        }
    #pragma unroll
    for (int nb = 0; nb < 4; nb++)
        #pragma unroll
        for (int s16 = 0; s16 < 4; s16++) {
            int rown = wn * 64 + nb * 16 + (lane & 7) + ((lane >> 4) << 3);
            boff[nb][s16] = swz(rown, s16 * 2 + ((lane >> 3) & 1));
        }

    float acc[2][8][4];
    #pragma unroll
    for (int mi = 0; mi < 2; mi++)
        #pragma unroll
        for (int nj = 0; nj < 8; nj++)
            #pragma unroll
            for (int q = 0; q < 4; q++) acc[mi][nj][q] = 0.f;

    load_stage(0, 0); CP_COMMIT();
    load_stage(1, 1); CP_COMMIT();

    for (int ch = 0; ch < 16; ch++) {
        CP_WAIT(1);
        __syncthreads();
        const int s = ch % 3;
        const uint32_t sb = dynu + s * SSZ;

        #pragma unroll
        for (int s16 = 0; s16 < 4; s16++) {
            uint32_t ah[2][4], al[2][4];
            #pragma unroll
            for (int mi = 0; mi < 2; mi++) {
                ldsm4(ah[mi], sb + aoff[mi][s16]);
                if (IS_UP) ldsm4(al[mi], sb + 16384 + aoff[mi][s16]);
            }
            uint32_t bh[4][4];
            #pragma unroll
            for (int nb = 0; nb < 4; nb++)
                ldsm4(bh[nb], sb + BOFF + boff[nb][s16]);
            #pragma unroll
            for (int mi = 0; mi < 2; mi++)
                #pragma unroll
                for (int nj = 0; nj < 8; nj++) {
                    const uint32_t* bph = &bh[nj >> 1][(nj & 1) * 2];
                    mma16816(acc[mi][nj], ah[mi], bph);
                    if (IS_UP) mma16816(acc[mi][nj], al[mi], bph);
                }
        }

        if (ch + 2 < 16) load_stage(ch + 2, (ch + 2) % 3);
        CP_COMMIT();
    }
    CP_WAIT(0);
    __syncthreads();

    // ---- epilogue through SMEM for coalesced global stores ----
    if (IS_UP) {
        // bias + ReLU -> fp16 hidden, single pass. stg pitch 132 u32.
        uint32_t* stg = reinterpret_cast<uint32_t*>(dynraw);
        #pragma unroll
        for (int mi = 0; mi < 2; mi++)
            #pragma unroll
            for (int nj = 0; nj < 8; nj++) {
                int col0 = wn * 64 + nj * 8 + 2 * qid;
                int r0 = wm * 32 + mi * 16 + gid;
                float b0 = bsh[col0], b1 = bsh[col0 + 1];
                float v0 = fmaxf(acc[mi][nj][0] + b0, 0.f);
                float v1 = fmaxf(acc[mi][nj][1] + b1, 0.f);
                float v2 = fmaxf(acc[mi][nj][2] + b0, 0.f);
                float v3 = fmaxf(acc[mi][nj][3] + b1, 0.f);
                __half2 p01 = __halves2half2(__float2half_rn(v0), __float2half_rn(v1));
                __half2 p23 = __halves2half2(__float2half_rn(v2), __float2half_rn(v3));
                int cp = col0 >> 1;
                stg[r0 * 132 + cp]       = *reinterpret_cast<uint32_t*>(&p01);
                stg[(r0 + 8) * 132 + cp] = *reinterpret_cast<uint32_t*>(&p23);
            }
        __syncthreads();
        uint32_t* dst32 = reinterpret_cast<uint32_t*>(g_hh);
        for (int i = tid; i < 4096; i += 512) {
            int row = i >> 5, q = i & 31;
            int r = rs[row];
            if (r < 0) continue;
            uint4 v = *reinterpret_cast<uint4*>(&stg[row * 132 + q * 4]);
            *reinterpret_cast<uint4*>(&dst32[(size_t)r * 512 + (n0 >> 1) + q * 4]) = v;
        }
    } else {
        // two 128-col fp32 passes, then zero-fill the other 768 cols.
        float* stgf = reinterpret_cast<float*>(dynraw);
        #pragma unroll
        for (int pass = 0; pass < 2; pass++) {
            if ((wn >> 1) == pass) {
                #pragma unroll
                for (int mi = 0; mi < 2; mi++)
                    #pragma unroll
                    for (int nj = 0; nj < 8; nj++) {
                        int col0 = wn * 64 + nj * 8 + 2 * qid;
                        int r0 = wm * 32 + mi * 16 + gid;
                        float b0 = bsh[col0], b1 = bsh[col0 + 1];
                        int cl = col0 - pass * 128;
                        stgf[r0 * 132 + cl]           = acc[mi][nj][0] + b0;
                        stgf[r0 * 132 + cl + 1]       = acc[mi][nj][1] + b1;
                        stgf[(r0 + 8) * 132 + cl]     = acc[mi][nj][2] + b0;
                        stgf[(r0 + 8) * 132 + cl + 1] = acc[mi][nj][3] + b1;
                    }
            }
            __syncthreads();
            for (int i = tid; i < 4096; i += 512) {
                int row = i >> 5, q = i & 31;
                int r = rs[row];
                if (r < 0) continue;
                float4 v = *reinterpret_cast<float4*>(&stgf[row * 132 + q * 4]);
                *reinterpret_cast<float4*>(&outp[(size_t)r * C_DIM + e * 256 + pass * 128 + q * 4]) = v;
            }
            __syncthreads();
        }
        const float4 z4 = make_float4(0.f, 0.f, 0.f, 0.f);
        for (int i = tid; i < 128 * 192; i += 512) {
            int row = i / 192, j = i - row * 192;
            int r = rs[row];
            if (r < 0) continue;
            int zcol = j * 4;
            if (zcol >= e * 256) zcol += 256;
            *reinterpret_cast<float4*>(&outp[(size_t)r * C_DIM + zcol]) = z4;
        }
    }
}

// ---------------------------------------------------------------------------
extern "C" void kernel_launch(void* const* d_in, const int* in_sizes, int n_in,
                              void* d_out, int out_size) {
    const float* x      = (const float*)d_in[0];
    const float* w_up   = (const float*)d_in[1];
    const float* b_up   = (const float*)d_in[2];
    const float* w_down = (const float*)d_in[3];
    const float* b_down = (const float*)d_in[4];
    float* out = (float*)d_out;

    const size_t out_elems = (size_t)N_ROWS * C_DIM;
    int write_gate = (out_size >= (int)(out_elems + (size_t)N_ROWS * NTILES)) ? 1 : 0;

    static int attr_done = 0;
    if (!attr_done) {
        cudaFuncSetAttribute(gemm_kernel<1>, cudaFuncAttributeMaxDynamicSharedMemorySize, 196608);
        cudaFuncSetAttribute(gemm_kernel<0>, cudaFuncAttributeMaxDynamicSharedMemorySize, 147456);
        attr_done = 1;
    }

    sig_sum_kernel<<<1024, 128>>>(w_up);                               // 0
    sign_kernel<<<16, 256>>>();                                        // 1
    route_kernel<<<N_ROWS, 128>>>(x, out + out_elems, write_gate);     // 2
    gemm_kernel<1><<<dim3(4, 128, NTILES), 512, 196608>>>(b_up, nullptr);   // 3 (profiled)
    split_wdown_kernel<<<1024, 256>>>(w_down);                         // 4
    gemm_kernel<0><<<dim3(1, 128, NTILES), 512, 147456>>>(b_down, out);     // 5
}

// round 7
// speedup vs baseline: 4.9408x; 1.0125x over previous
#include <cuda_runtime.h>
#include <cuda_fp16.h>
#include <cstdint>

#define N_ROWS 16384
#define C_DIM  1024
#define NTILES 4

// ---------------- device global scratch (no allocations allowed) ----------------
__device__ float g_part[32 * 4096];       // deterministic partial column sums
__device__ float g_sig[NTILES * C_DIM];
__device__ int   g_cnt[NTILES];
__device__ int   g_rows[NTILES * N_ROWS];
__device__ __half g_xh[(size_t)N_ROWS * C_DIM];
__device__ __half g_xl[(size_t)N_ROWS * C_DIM];
__device__ __half g_wuh[(size_t)4096 * 1024];
__device__ __half g_wdh[(size_t)1024 * 1024];   // 4 diag blocks [e*256+n][k]
__device__ __half g_hh[(size_t)N_ROWS * 1024];  // hidden (fp16)

// ---------------- PTX helpers ----------------
static __device__ __forceinline__ uint32_t smem_u32(const void* p) {
    uint32_t a;
    asm("{ .reg .u64 t; cvta.to.shared.u64 t, %1; cvt.u32.u64 %0, t; }" : "=r"(a) : "l"(p));
    return a;
}
static __device__ __forceinline__ void cp16(uint32_t dst, const void* src, int sz) {
    asm volatile("cp.async.cg.shared.global [%0], [%1], 16, %2;" :: "r"(dst), "l"(src), "r"(sz));
}
#define CP_COMMIT() asm volatile("cp.async.commit_group;" ::: "memory")
#define CP_WAIT(n)  asm volatile("cp.async.wait_group %0;" :: "n"(n) : "memory")

static __device__ __forceinline__ void ldsm4(uint32_t* r, uint32_t addr) {
    asm volatile("ldmatrix.sync.aligned.m8n8.x4.shared.b16 {%0,%1,%2,%3}, [%4];"
                 : "=r"(r[0]), "=r"(r[1]), "=r"(r[2]), "=r"(r[3]) : "r"(addr));
}
static __device__ __forceinline__ void mma16816(float* c, const uint32_t* a, const uint32_t* b) {
    asm volatile("mma.sync.aligned.m16n8k16.row.col.f32.f16.f16.f32 "
                 "{%0,%1,%2,%3}, {%4,%5,%6,%7}, {%8,%9}, {%0,%1,%2,%3};"
                 : "+f"(c[0]), "+f"(c[1]), "+f"(c[2]), "+f"(c[3])
                 : "r"(a[0]), "r"(a[1]), "r"(a[2]), "r"(a[3]), "r"(b[0]), "r"(b[1]));
}

// 128B-row swizzle (Swizzle<3,4,3>): 16B-group g' = g ^ (row & 7)
static __device__ __forceinline__ uint32_t swz(int row, int g) {
    return (uint32_t)row * 128 + (uint32_t)((g ^ (row & 7)) << 4);
}

// ---------------------------------------------------------------------------
// Phase 1: partial column sums of w_up (32-row chunks) FUSED with fp16 convert.
__global__ void sig_sum_kernel(const float* __restrict__ w_up) {
    int bx = blockIdx.x;
    int t  = bx >> 8, cb = (bx >> 5) & 7, rc = bx & 31;
    int c  = cb * 128 + threadIdx.x;
    int row0 = t * 1024 + rc * 32;
    const float* base = w_up + (size_t)row0 * C_DIM + c;
    float s = 0.f;
    #pragma unroll 8
    for (int r = 0; r < 32; r++) {
        float v = base[(size_t)r * C_DIM];
        s += v;
        g_wuh[(size_t)(row0 + r) * C_DIM + c] = __float2half_rn(v);
    }
    g_part[rc * 4096 + t * C_DIM + c] = s;
}

// Phase 2: fixed-order combine + sign; also resets routing counters.
__global__ void sign_kernel() {
    int i = blockIdx.x * 256 + threadIdx.x;
    if (blockIdx.x == 0 && threadIdx.x < NTILES) g_cnt[threadIdx.x] = 0;
    float s = 0.f;
    #pragma unroll
    for (int rc = 0; rc < 32; rc++) s += g_part[rc * 4096 + i];
    g_sig[i] = (s > 0.f) ? 1.f : ((s < 0.f) ? -1.f : 0.f);
}

// routing (fp32, exact argmax semantics) + fp16 hi/lo split of x, vectorized.
__global__ void route_kernel(const float* __restrict__ x,
                             float* __restrict__ gate_out, int write_gate) {
    __shared__ float red[NTILES][128];
    int n = blockIdx.x;
    int tid = threadIdx.x;
    const float4* xr = reinterpret_cast<const float4*>(x + (size_t)n * C_DIM);
    float a[NTILES] = {0.f, 0.f, 0.f, 0.f};
    __half hh[8], hl[8];
    #pragma unroll
    for (int q = 0; q < 2; q++) {
        int k4 = tid * 2 + q;              // float4 index 0..255
        float4 v = xr[k4];
        float vv[4] = {v.x, v.y, v.z, v.w};
        #pragma unroll
        for (int t = 0; t < NTILES; t++) {
            const float4 sg = reinterpret_cast<const float4*>(g_sig + t * C_DIM)[k4];
            a[t] += v.x * sg.x + v.y * sg.y + v.z * sg.z + v.w * sg.w;
        }
        #pragma unroll
        for (int j = 0; j < 4; j++) {
            __half h = __float2half_rn(vv[j]);
            hh[q * 4 + j] = h;
            hl[q * 4 + j] = __float2half_rn(vv[j] - __half2float(h));
        }
    }
    *reinterpret_cast<uint4*>(g_xh + (size_t)n * C_DIM + tid * 8) = *reinterpret_cast<uint4*>(hh);
    *reinterpret_cast<uint4*>(g_xl + (size_t)n * C_DIM + tid * 8) = *reinterpret_cast<uint4*>(hl);

    #pragma unroll
    for (int t = 0; t < NTILES; t++) red[t][tid] = a[t];
    __syncthreads();
    for (int s = 64; s > 0; s >>= 1) {
        if (tid < s) {
            #pragma unroll
            for (int t = 0; t < NTILES; t++) red[t][tid] += red[t][tid + s];
        }
        __syncthreads();
    }
    if (tid == 0) {
        float best = red[0][0];
        int w = 0;
        #pragma unroll
        for (int t = 1; t < NTILES; t++)
            if (red[t][0] > best) { best = red[t][0]; w = t; }
        int pos = atomicAdd(&g_cnt[w], 1);
        g_rows[w * N_ROWS + pos] = n;
        if (write_gate) {
            #pragma unroll
            for (int t = 0; t < NTILES; t++)
                gate_out[(size_t)n * NTILES + t] = (t == w) ? 1.f : 0.f;
        }
    }
}

// w_down diag blocks -> fp16, float4 vectorized: 256K float4
__global__ void split_wdown_kernel(const float* __restrict__ w) {
    size_t i = (size_t)blockIdx.x * 256 + threadIdx.x;   // float4 index
    size_t el = i * 4;
    int e = (int)(el >> 18);
    int n = (int)((el >> 10) & 255);
    int k = (int)(el & 1023);
    float4 v = *reinterpret_cast<const float4*>(w + (size_t)(e * 256 + n) * 4096 + e * 1024 + k);
    __half2 a = __halves2half2(__float2half_rn(v.x), __float2half_rn(v.y));
    __half2 b = __halves2half2(__float2half_rn(v.z), __float2half_rn(v.w));
    reinterpret_cast<__half2*>(g_wdh)[i * 2]     = a;
    reinterpret_cast<__half2*>(g_wdh)[i * 2 + 1] = b;
}

// ---------------------------------------------------------------------------
// UP GEMM: 2-term fp16 split (A = xh + xl, B = wuh), fp32 accum.
// CTA: 128 gathered rows x 128 cols, 256 threads, 2 CTAs/SM.
// K = 1024 in 16 chunks of 64. Stage 48KB: Ah(16K) | Al(16K) | B(16K),
// 128B rows Swizzle<3,4,3>. 2-stage double buffer (96KB dynamic).
// 8 warps 4m x 2n, warp tile 32x64. Epilogue: bias+ReLU -> g_hh (fp16).
// ---------------------------------------------------------------------------
__global__ void __launch_bounds__(256, 2)
gemm_up_kernel(const float* __restrict__ bias)
{
    const int e   = blockIdx.z;
    const int cnt = g_cnt[e];
    const int m0  = blockIdx.y * 128;
    if (m0 >= cnt) return;
    const int n0  = blockIdx.x * 128;
    const int tid = threadIdx.x;

    extern __shared__ __align__(1024) uint8_t dynraw[];
    __shared__ int rs[128];
    __shared__ float bsh[128];
    const uint32_t dynu = smem_u32(dynraw);

    const int brow0 = e * 1024 + n0;

    if (tid < 128) {
        int m = m0 + tid;
        rs[tid]  = (m < cnt) ? g_rows[e * N_ROWS + m] : -1;
        bsh[tid] = bias[brow0 + tid];
    }
    __syncthreads();

    // stage loader: chunk ch (64 k-vals) into slot {0,1}
    auto load_stage = [&](int ch, int slot) {
        const uint32_t sb = dynu + slot * 49152;
        #pragma unroll
        for (int l = 0; l < 4; l++) {        // A: 128 rows x 8 groups = 1024 sites
            int i = tid * 4 + l;
            int row = i >> 3, g = i & 7;
            uint32_t off = swz(row, g);
            int r = rs[row];
            const size_t ak = (size_t)(r < 0 ? 0 : r) * 1024 + ch * 64 + g * 8;
            int sz = (r < 0) ? 0 : 16;
            cp16(sb + off,         g_xh + ak, sz);
            cp16(sb + 16384 + off, g_xl + ak, sz);
        }
        #pragma unroll
        for (int l = 0; l < 4; l++) {        // B: 128 rows x 8 groups = 1024 sites
            int j = tid * 4 + l;
            int row = j >> 3, g = j & 7;
            uint32_t off = swz(row, g);
            const size_t bk = (size_t)(brow0 + row) * 1024 + ch * 64 + g * 8;
            cp16(sb + 32768 + off, g_wuh + bk, 16);
        }
    };

    const int lane = tid & 31, w = tid >> 5;
    const int wm = w >> 1, wn = w & 1;
    const int gid = lane >> 2, qid = lane & 3;

    uint32_t aoff[2][4], boff[4][4];
    #pragma unroll
    for (int mi = 0; mi < 2; mi++)
        #pragma unroll
        for (int s16 = 0; s16 < 4; s16++) {
            int row = wm * 32 + mi * 16 + (lane & 15);
            aoff[mi][s16] = swz(row, s16 * 2 + (lane >> 4));
        }
    #pragma unroll
    for (int nb = 0; nb < 4; nb++)
        #pragma unroll
        for (int s16 = 0; s16 < 4; s16++) {
            int rown = wn * 64 + nb * 16 + (lane & 7) + ((lane >> 4) << 3);
            boff[nb][s16] = swz(rown, s16 * 2 + ((lane >> 3) & 1));
        }

    float acc[2][8][4];
    #pragma unroll
    for (int mi = 0; mi < 2; mi++)
        #pragma unroll
        for (int nj = 0; nj < 8; nj++)
            #pragma unroll
            for (int q = 0; q < 4; q++) acc[mi][nj][q] = 0.f;

    load_stage(0, 0); CP_COMMIT();

    for (int ch = 0; ch < 16; ch++) {
        if (ch + 1 < 16) {
            load_stage(ch + 1, (ch + 1) & 1);
            CP_COMMIT();
            CP_WAIT(1);
        } else {
            CP_WAIT(0);
        }
        __syncthreads();
        const uint32_t sb = dynu + (ch & 1) * 49152;

        #pragma unroll
        for (int s16 = 0; s16 < 4; s16++) {
            uint32_t ah[2][4], al[2][4];
            #pragma unroll
            for (int mi = 0; mi < 2; mi++) {
                ldsm4(ah[mi], sb + aoff[mi][s16]);
                ldsm4(al[mi], sb + 16384 + aoff[mi][s16]);
            }
            uint32_t bh[4][4];
            #pragma unroll
            for (int nb = 0; nb < 4; nb++)
                ldsm4(bh[nb], sb + 32768 + boff[nb][s16]);
            #pragma unroll
            for (int mi = 0; mi < 2; mi++)
                #pragma unroll
                for (int nj = 0; nj < 8; nj++) {
                    const uint32_t* bph = &bh[nj >> 1][(nj & 1) * 2];
                    mma16816(acc[mi][nj], ah[mi], bph);
                    mma16816(acc[mi][nj], al[mi], bph);
                }
        }
        __syncthreads();   // protect slot reuse by the next-next load
    }

    // ---- epilogue: bias + ReLU -> fp16, SMEM stage, coalesced stores ----
    uint32_t* stg = reinterpret_cast<uint32_t*>(dynraw);   // pitch 68 u32
    #pragma unroll
    for (int mi = 0; mi < 2; mi++)
        #pragma unroll
        for (int nj = 0; nj < 8; nj++) {
            int col0 = wn * 64 + nj * 8 + 2 * qid;
            int r0 = wm * 32 + mi * 16 + gid;
            float b0 = bsh[col0], b1 = bsh[col0 + 1];
            float v0 = fmaxf(acc[mi][nj][0] + b0, 0.f);
            float v1 = fmaxf(acc[mi][nj][1] + b1, 0.f);
            float v2 = fmaxf(acc[mi][nj][2] + b0, 0.f);
            float v3 = fmaxf(acc[mi][nj][3] + b1, 0.f);
            __half2 p01 = __halves2half2(__float2half_rn(v0), __float2half_rn(v1));
            __half2 p23 = __halves2half2(__float2half_rn(v2), __float2half_rn(v3));
            int cp = col0 >> 1;
            stg[r0 * 68 + cp]       = *reinterpret_cast<uint32_t*>(&p01);
            stg[(r0 + 8) * 68 + cp] = *reinterpret_cast<uint32_t*>(&p23);
        }
    __syncthreads();
    uint32_t* dst32 = reinterpret_cast<uint32_t*>(g_hh);
    for (int i = tid; i < 2048; i += 256) {
        int row = i >> 4, q = i & 15;
        int r = rs[row];
        if (r < 0) continue;
        uint4 v = *reinterpret_cast<uint4*>(&stg[row * 68 + q * 4]);
        *reinterpret_cast<uint4*>(&dst32[(size_t)r * 512 + (n0 >> 1) + q * 4]) = v;
    }
}

// ---------------------------------------------------------------------------
// DOWN GEMM: 1-term fp16 (A = hh, B = wdh), fp32 accum.
// CTA: 128 gathered rows x 256 cols, 512 threads, K = 1024 in 16 chunks of 64.
// Stage 48KB: A(16K) | B(32K); 3-stage. Epilogue: bias -> out slice + zeros.
// ---------------------------------------------------------------------------
__global__ void __launch_bounds__(512, 1)
gemm_down_kernel(const float* __restrict__ bias, float* __restrict__ outp)
{
    const int e   = blockIdx.z;
    const int cnt = g_cnt[e];
    const int m0  = blockIdx.y * 128;
    if (m0 >= cnt) return;
    const int tid = threadIdx.x;

    extern __shared__ __align__(1024) uint8_t dynraw[];
    __shared__ int rs[128];
    __shared__ float bsh[256];
    const uint32_t dynu = smem_u32(dynraw);

    const int brow0 = e * 256;

    if (tid < 128) {
        int m = m0 + tid;
        rs[tid] = (m < cnt) ? g_rows[e * N_ROWS + m] : -1;
    }
    if (tid < 256) bsh[tid] = bias[brow0 + tid];
    __syncthreads();

    auto load_stage = [&](int ch, int slot) {
        const uint32_t sb = dynu + slot * 49152;
        #pragma unroll
        for (int l = 0; l < 2; l++) {        // A: 128 rows x 8 groups
            int i = tid * 2 + l;
            int row = i >> 3, g = i & 7;
            uint32_t off = swz(row, g);
            int r = rs[row];
            const size_t ak = (size_t)(r < 0 ? 0 : r) * 1024 + ch * 64 + g * 8;
            cp16(sb + off, g_hh + ak, (r < 0) ? 0 : 16);
        }
        #pragma unroll
        for (int l = 0; l < 4; l++) {        // B: 256 rows x 8 groups
            int j = tid * 4 + l;
            int row = j >> 3, g = j & 7;
            uint32_t off = swz(row, g);
            const size_t bk = (size_t)(brow0 + row) * 1024 + ch * 64 + g * 8;
            cp16(sb + 16384 + off, g_wdh + bk, 16);
        }
    };

    const int lane = tid & 31, w = tid >> 5;
    const int wm = w >> 2, wn = w & 3;
    const int gid = lane >> 2, qid = lane & 3;

    uint32_t aoff[2][4], boff[4][4];
    #pragma unroll
    for (int mi = 0; mi < 2; mi++)
        #pragma unroll
        for (int s16 = 0; s16 < 4; s16++) {
            int row = wm * 32 + mi * 16 + (lane & 15);
            aoff[mi][s16] = swz(row, s16 * 2 + (lane >> 4));
        }
    #pragma unroll
    for (int nb = 0; nb < 4; nb++)
        #pragma unroll
        for (int s16 = 0; s16 < 4; s16++) {
            int rown = wn * 64 + nb * 16 + (lane & 7) + ((lane >> 4) << 3);
            boff[nb][s16] = swz(rown, s16 * 2 + ((lane >> 3) & 1));
        }

    float acc[2][8][4];
    #pragma unroll
    for (int mi = 0; mi < 2; mi++)
        #pragma unroll
        for (int nj = 0; nj < 8; nj++)
            #pragma unroll
            for (int q = 0; q < 4; q++) acc[mi][nj][q] = 0.f;

    load_stage(0, 0); CP_COMMIT();
    load_stage(1, 1); CP_COMMIT();

    for (int ch = 0; ch < 16; ch++) {
        CP_WAIT(1);
        __syncthreads();
        const int s = ch % 3;
        const uint32_t sb = dynu + s * 49152;

        #pragma unroll
        for (int s16 = 0; s16 < 4; s16++) {
            uint32_t ah[2][4];
            #pragma unroll
            for (int mi = 0; mi < 2; mi++)
                ldsm4(ah[mi], sb + aoff[mi][s16]);
            uint32_t bh[4][4];
            #pragma unroll
            for (int nb = 0; nb < 4; nb++)
                ldsm4(bh[nb], sb + 16384 + boff[nb][s16]);
            #pragma unroll
            for (int mi = 0; mi < 2; mi++)
                #pragma unroll
                for (int nj = 0; nj < 8; nj++)
                    mma16816(acc[mi][nj], ah[mi], &bh[nj >> 1][(nj & 1) * 2]);
        }

        if (ch + 2 < 16) load_stage(ch + 2, (ch + 2) % 3);
        CP_COMMIT();
    }
    CP_WAIT(0);
    __syncthreads();

    // epilogue: two 128-col fp32 passes + zero-fill other 768 cols
    float* stgf = reinterpret_cast<float*>(dynraw);
    #pragma unroll
    for (int pass = 0; pass < 2; pass++) {
        if ((wn >> 1) == pass) {
            #pragma unroll
            for (int mi = 0; mi < 2; mi++)
                #pragma unroll
                for (int nj = 0; nj < 8; nj++) {
                    int col0 = wn * 64 + nj * 8 + 2 * qid;
                    int r0 = wm * 32 + mi * 16 + gid;
                    float b0 = bsh[col0], b1 = bsh[col0 + 1];
                    int cl = col0 - pass * 128;
                    stgf[r0 * 132 + cl]           = acc[mi][nj][0] + b0;
                    stgf[r0 * 132 + cl + 1]       = acc[mi][nj][1] + b1;
                    stgf[(r0 + 8) * 132 + cl]     = acc[mi][nj][2] + b0;
                    stgf[(r0 + 8) * 132 + cl + 1] = acc[mi][nj][3] + b1;
                }
        }
        __syncthreads();
        for (int i = tid; i < 4096; i += 512) {
            int row = i >> 5, q = i & 31;
            int r = rs[row];
            if (r < 0) continue;
            float4 v = *reinterpret_cast<float4*>(&stgf[row * 132 + q * 4]);
            *reinterpret_cast<float4*>(&outp[(size_t)r * C_DIM + e * 256 + pass * 128 + q * 4]) = v;
        }
        __syncthreads();
    }
    const float4 z4 = make_float4(0.f, 0.f, 0.f, 0.f);
    for (int i = tid; i < 128 * 192; i += 512) {
        int row = i / 192, j = i - row * 192;
        int r = rs[row];
        if (r < 0) continue;
        int zcol = j * 4;
        if (zcol >= e * 256) zcol += 256;
        *reinterpret_cast<float4*>(&outp[(size_t)r * C_DIM + zcol]) = z4;
    }
}

// ---------------------------------------------------------------------------
extern "C" void kernel_launch(void* const* d_in, const int* in_sizes, int n_in,
                              void* d_out, int out_size) {
    const float* x      = (const float*)d_in[0];
    const float* w_up   = (const float*)d_in[1];
    const float* b_up   = (const float*)d_in[2];
    const float* w_down = (const float*)d_in[3];
    const float* b_down = (const float*)d_in[4];
    float* out = (float*)d_out;

    const size_t out_elems = (size_t)N_ROWS * C_DIM;
    int write_gate = (out_size >= (int)(out_elems + (size_t)N_ROWS * NTILES)) ? 1 : 0;

    static int attr_done = 0;
    if (!attr_done) {
        cudaFuncSetAttribute(gemm_up_kernel,   cudaFuncAttributeMaxDynamicSharedMemorySize, 98304);
        cudaFuncSetAttribute(gemm_down_kernel, cudaFuncAttributeMaxDynamicSharedMemorySize, 147456);
        attr_done = 1;
    }

    sig_sum_kernel<<<1024, 128>>>(w_up);                               // 0
    sign_kernel<<<16, 256>>>();                                        // 1
    route_kernel<<<N_ROWS, 128>>>(x, out + out_elems, write_gate);     // 2
    gemm_up_kernel<<<dim3(8, 128, NTILES), 256, 98304>>>(b_up);        // 3 (profiled)
    split_wdown_kernel<<<1024, 256>>>(w_down);                         // 4
    gemm_down_kernel<<<dim3(1, 128, NTILES), 512, 147456>>>(b_down, out); // 5
}

// round 8
// speedup vs baseline: 7.0798x; 1.4329x over previous
#include <cuda_runtime.h>
#include <cuda_fp16.h>
#include <cstdint>

#define N_ROWS 16384
#define C_DIM  1024
#define NTILES 4

// ---------------- device global scratch (no allocations allowed) ----------------
__device__ float g_part[32 * 4096];       // deterministic partial column sums
__device__ float g_sig[NTILES * C_DIM];
__device__ int   g_cnt[NTILES];
__device__ int   g_rows[NTILES * N_ROWS];
__device__ __half g_xh[(size_t)N_ROWS * C_DIM];
__device__ __half g_wuh[(size_t)4096 * 1024];
__device__ __half g_wdh[(size_t)1024 * 1024];   // 4 diag blocks [e*256+n][k]
__device__ __half g_hh[(size_t)N_ROWS * 1024];  // hidden (fp16)

// ---------------- PTX helpers ----------------
static __device__ __forceinline__ uint32_t smem_u32(const void* p) {
    uint32_t a;
    asm("{ .reg .u64 t; cvta.to.shared.u64 t, %1; cvt.u32.u64 %0, t; }" : "=r"(a) : "l"(p));
    return a;
}
static __device__ __forceinline__ void cp16(uint32_t dst, const void* src, int sz) {
    asm volatile("cp.async.cg.shared.global [%0], [%1], 16, %2;" :: "r"(dst), "l"(src), "r"(sz));
}
#define CP_COMMIT() asm volatile("cp.async.commit_group;" ::: "memory")
#define CP_WAIT(n)  asm volatile("cp.async.wait_group %0;" :: "n"(n) : "memory")

static __device__ __forceinline__ void ldsm4(uint32_t* r, uint32_t addr) {
    asm volatile("ldmatrix.sync.aligned.m8n8.x4.shared.b16 {%0,%1,%2,%3}, [%4];"
                 : "=r"(r[0]), "=r"(r[1]), "=r"(r[2]), "=r"(r[3]) : "r"(addr));
}
static __device__ __forceinline__ void mma16816(float* c, const uint32_t* a, const uint32_t* b) {
    asm volatile("mma.sync.aligned.m16n8k16.row.col.f32.f16.f16.f32 "
                 "{%0,%1,%2,%3}, {%4,%5,%6,%7}, {%8,%9}, {%0,%1,%2,%3};"
                 : "+f"(c[0]), "+f"(c[1]), "+f"(c[2]), "+f"(c[3])
                 : "r"(a[0]), "r"(a[1]), "r"(a[2]), "r"(a[3]), "r"(b[0]), "r"(b[1]));
}

// 128B-row swizzle (Swizzle<3,4,3>): 16B-group g' = g ^ (row & 7)
static __device__ __forceinline__ uint32_t swz(int row, int g) {
    return (uint32_t)row * 128 + (uint32_t)((g ^ (row & 7)) << 4);
}

// ---------------------------------------------------------------------------
// Phase 1: partial column sums of w_up (32-row chunks) FUSED with fp16 convert.
__global__ void sig_sum_kernel(const float* __restrict__ w_up) {
    int bx = blockIdx.x;
    int t  = bx >> 8, cb = (bx >> 5) & 7, rc = bx & 31;
    int c  = cb * 128 + threadIdx.x;
    int row0 = t * 1024 + rc * 32;
    const float* base = w_up + (size_t)row0 * C_DIM + c;
    float s = 0.f;
    #pragma unroll 8
    for (int r = 0; r < 32; r++) {
        float v = base[(size_t)r * C_DIM];
        s += v;
        g_wuh[(size_t)(row0 + r) * C_DIM + c] = __float2half_rn(v);
    }
    g_part[rc * 4096 + t * C_DIM + c] = s;
}

// Phase 2: fixed-order combine + sign; also resets routing counters.
__global__ void sign_kernel() {
    int i = blockIdx.x * 256 + threadIdx.x;
    if (blockIdx.x == 0 && threadIdx.x < NTILES) g_cnt[threadIdx.x] = 0;
    float s = 0.f;
    #pragma unroll
    for (int rc = 0; rc < 32; rc++) s += g_part[rc * 4096 + i];
    g_sig[i] = (s > 0.f) ? 1.f : ((s < 0.f) ? -1.f : 0.f);
}

// routing (fp32, exact argmax semantics) + fp16 convert of x, vectorized.
__global__ void route_kernel(const float* __restrict__ x,
                             float* __restrict__ gate_out, int write_gate) {
    __shared__ float red[NTILES][128];
    int n = blockIdx.x;
    int tid = threadIdx.x;
    const float4* xr = reinterpret_cast<const float4*>(x + (size_t)n * C_DIM);
    float a[NTILES] = {0.f, 0.f, 0.f, 0.f};
    __half hh[8];
    #pragma unroll
    for (int q = 0; q < 2; q++) {
        int k4 = tid * 2 + q;              // float4 index 0..255
        float4 v = xr[k4];
        #pragma unroll
        for (int t = 0; t < NTILES; t++) {
            const float4 sg = reinterpret_cast<const float4*>(g_sig + t * C_DIM)[k4];
            a[t] += v.x * sg.x + v.y * sg.y + v.z * sg.z + v.w * sg.w;
        }
        hh[q * 4 + 0] = __float2half_rn(v.x);
        hh[q * 4 + 1] = __float2half_rn(v.y);
        hh[q * 4 + 2] = __float2half_rn(v.z);
        hh[q * 4 + 3] = __float2half_rn(v.w);
    }
    *reinterpret_cast<uint4*>(g_xh + (size_t)n * C_DIM + tid * 8) = *reinterpret_cast<uint4*>(hh);

    #pragma unroll
    for (int t = 0; t < NTILES; t++) red[t][tid] = a[t];
    __syncthreads();
    for (int s = 64; s > 0; s >>= 1) {
        if (tid < s) {
            #pragma unroll
            for (int t = 0; t < NTILES; t++) red[t][tid] += red[t][tid + s];
        }
        __syncthreads();
    }
    if (tid == 0) {
        float best = red[0][0];
        int w = 0;
        #pragma unroll
        for (int t = 1; t < NTILES; t++)
            if (red[t][0] > best) { best = red[t][0]; w = t; }
        int pos = atomicAdd(&g_cnt[w], 1);
        g_rows[w * N_ROWS + pos] = n;
        if (write_gate) {
            #pragma unroll
            for (int t = 0; t < NTILES; t++)
                gate_out[(size_t)n * NTILES + t] = (t == w) ? 1.f : 0.f;
        }
    }
}

// w_down diag blocks -> fp16, float4 vectorized: 256K float4
__global__ void split_wdown_kernel(const float* __restrict__ w) {
    size_t i = (size_t)blockIdx.x * 256 + threadIdx.x;   // float4 index
    size_t el = i * 4;
    int e = (int)(el >> 18);
    int n = (int)((el >> 10) & 255);
    int k = (int)(el & 1023);
    float4 v = *reinterpret_cast<const float4*>(w + (size_t)(e * 256 + n) * 4096 + e * 1024 + k);
    __half2 a = __halves2half2(__float2half_rn(v.x), __float2half_rn(v.y));
    __half2 b = __halves2half2(__float2half_rn(v.z), __float2half_rn(v.w));
    reinterpret_cast<__half2*>(g_wdh)[i * 2]     = a;
    reinterpret_cast<__half2*>(g_wdh)[i * 2 + 1] = b;
}

// ---------------------------------------------------------------------------
// UP GEMM: plain fp16 (A = xh, B = wuh), fp32 accum.
// CTA: 128 gathered rows x 128 cols, 256 threads, 2 CTAs/SM.
// K = 1024 in 16 chunks of 64. Stage 32KB: A(16K) | B(16K), 128B rows
// Swizzle<3,4,3>. 3-stage pipeline, ONE barrier per chunk (96KB dynamic).
// 8 warps 4m x 2n, warp tile 32x64. Epilogue: bias+ReLU -> g_hh (fp16).
// ---------------------------------------------------------------------------
__global__ void __launch_bounds__(256, 2)
gemm_up_kernel(const float* __restrict__ bias)
{
    const int e   = blockIdx.z;
    const int cnt = g_cnt[e];
    const int m0  = blockIdx.y * 128;
    if (m0 >= cnt) return;
    const int n0  = blockIdx.x * 128;
    const int tid = threadIdx.x;

    extern __shared__ __align__(1024) uint8_t dynraw[];
    __shared__ int rs[128];
    __shared__ float bsh[128];
    const uint32_t dynu = smem_u32(dynraw);

    const int brow0 = e * 1024 + n0;

    if (tid < 128) {
        int m = m0 + tid;
        rs[tid]  = (m < cnt) ? g_rows[e * N_ROWS + m] : -1;
        bsh[tid] = bias[brow0 + tid];
    }
    __syncthreads();

    // stage loader: chunk ch (64 k-vals) into slot {0,1,2}
    auto load_stage = [&](int ch, int slot) {
        const uint32_t sb = dynu + slot * 32768;
        #pragma unroll
        for (int l = 0; l < 4; l++) {        // A: 128 rows x 8 groups = 1024 sites
            int i = tid * 4 + l;
            int row = i >> 3, g = i & 7;
            uint32_t off = swz(row, g);
            int r = rs[row];
            const size_t ak = (size_t)(r < 0 ? 0 : r) * 1024 + ch * 64 + g * 8;
            cp16(sb + off, g_xh + ak, (r < 0) ? 0 : 16);
        }
        #pragma unroll
        for (int l = 0; l < 4; l++) {        // B: 128 rows x 8 groups = 1024 sites
            int j = tid * 4 + l;
            int row = j >> 3, g = j & 7;
            uint32_t off = swz(row, g);
            const size_t bk = (size_t)(brow0 + row) * 1024 + ch * 64 + g * 8;
            cp16(sb + 16384 + off, g_wuh + bk, 16);
        }
    };

    const int lane = tid & 31, w = tid >> 5;
    const int wm = w >> 1, wn = w & 1;
    const int gid = lane >> 2, qid = lane & 3;

    uint32_t aoff[2][4], boff[4][4];
    #pragma unroll
    for (int mi = 0; mi < 2; mi++)
        #pragma unroll
        for (int s16 = 0; s16 < 4; s16++) {
            int row = wm * 32 + mi * 16 + (lane & 15);
            aoff[mi][s16] = swz(row, s16 * 2 + (lane >> 4));
        }
    #pragma unroll
    for (int nb = 0; nb < 4; nb++)
        #pragma unroll
        for (int s16 = 0; s16 < 4; s16++) {
            int rown = wn * 64 + nb * 16 + (lane & 7) + ((lane >> 4) << 3);
            boff[nb][s16] = swz(rown, s16 * 2 + ((lane >> 3) & 1));
        }

    float acc[2][8][4];
    #pragma unroll
    for (int mi = 0; mi < 2; mi++)
        #pragma unroll
        for (int nj = 0; nj < 8; nj++)
            #pragma unroll
            for (int q = 0; q < 4; q++) acc[mi][nj][q] = 0.f;

    load_stage(0, 0); CP_COMMIT();
    load_stage(1, 1); CP_COMMIT();

    for (int ch = 0; ch < 16; ch++) {
        CP_WAIT(1);
        __syncthreads();
        const uint32_t sb = dynu + (ch % 3) * 32768;

        #pragma unroll
        for (int s16 = 0; s16 < 4; s16++) {
            uint32_t ah[2][4];
            #pragma unroll
            for (int mi = 0; mi < 2; mi++)
                ldsm4(ah[mi], sb + aoff[mi][s16]);
            uint32_t bh[4][4];
            #pragma unroll
            for (int nb = 0; nb < 4; nb++)
                ldsm4(bh[nb], sb + 16384 + boff[nb][s16]);
            #pragma unroll
            for (int mi = 0; mi < 2; mi++)
                #pragma unroll
                for (int nj = 0; nj < 8; nj++)
                    mma16816(acc[mi][nj], ah[mi], &bh[nj >> 1][(nj & 1) * 2]);
        }

        if (ch + 2 < 16) load_stage(ch + 2, (ch + 2) % 3);
        CP_COMMIT();
    }
    CP_WAIT(0);
    __syncthreads();

    // ---- epilogue: bias + ReLU -> fp16, SMEM stage, coalesced stores ----
    uint32_t* stg = reinterpret_cast<uint32_t*>(dynraw);   // pitch 68 u32
    #pragma unroll
    for (int mi = 0; mi < 2; mi++)
        #pragma unroll
        for (int nj = 0; nj < 8; nj++) {
            int col0 = wn * 64 + nj * 8 + 2 * qid;
            int r0 = wm * 32 + mi * 16 + gid;
            float b0 = bsh[col0], b1 = bsh[col0 + 1];
            float v0 = fmaxf(acc[mi][nj][0] + b0, 0.f);
            float v1 = fmaxf(acc[mi][nj][1] + b1, 0.f);
            float v2 = fmaxf(acc[mi][nj][2] + b0, 0.f);
            float v3 = fmaxf(acc[mi][nj][3] + b1, 0.f);
            __half2 p01 = __halves2half2(__float2half_rn(v0), __float2half_rn(v1));
            __half2 p23 = __halves2half2(__float2half_rn(v2), __float2half_rn(v3));
            int cp = col0 >> 1;
            stg[r0 * 68 + cp]       = *reinterpret_cast<uint32_t*>(&p01);
            stg[(r0 + 8) * 68 + cp] = *reinterpret_cast<uint32_t*>(&p23);
        }
    __syncthreads();
    uint32_t* dst32 = reinterpret_cast<uint32_t*>(g_hh);
    for (int i = tid; i < 2048; i += 256) {
        int row = i >> 4, q = i & 15;
        int r = rs[row];
        if (r < 0) continue;
        uint4 v = *reinterpret_cast<uint4*>(&stg[row * 68 + q * 4]);
        *reinterpret_cast<uint4*>(&dst32[(size_t)r * 512 + (n0 >> 1) + q * 4]) = v;
    }
}

// ---------------------------------------------------------------------------
// DOWN GEMM: 1-term fp16 (A = hh, B = wdh), fp32 accum.
// CTA: 128 gathered rows x 256 cols, 512 threads, K = 1024 in 16 chunks of 64.
// Stage 48KB: A(16K) | B(32K); 3-stage. Epilogue: bias -> out slice + zeros.
// ---------------------------------------------------------------------------
__global__ void __launch_bounds__(512, 1)
gemm_down_kernel(const float* __restrict__ bias, float* __restrict__ outp)
{
    const int e   = blockIdx.z;
    const int cnt = g_cnt[e];
    const int m0  = blockIdx.y * 128;
    if (m0 >= cnt) return;
    const int tid = threadIdx.x;

    extern __shared__ __align__(1024) uint8_t dynraw[];
    __shared__ int rs[128];
    __shared__ float bsh[256];
    const uint32_t dynu = smem_u32(dynraw);

    const int brow0 = e * 256;

    if (tid < 128) {
        int m = m0 + tid;
        rs[tid] = (m < cnt) ? g_rows[e * N_ROWS + m] : -1;
    }
    if (tid < 256) bsh[tid] = bias[brow0 + tid];
    __syncthreads();

    auto load_stage = [&](int ch, int slot) {
        const uint32_t sb = dynu + slot * 49152;
        #pragma unroll
        for (int l = 0; l < 2; l++) {        // A: 128 rows x 8 groups
            int i = tid * 2 + l;
            int row = i >> 3, g = i & 7;
            uint32_t off = swz(row, g);
            int r = rs[row];
            const size_t ak = (size_t)(r < 0 ? 0 : r) * 1024 + ch * 64 + g * 8;
            cp16(sb + off, g_hh + ak, (r < 0) ? 0 : 16);
        }
        #pragma unroll
        for (int l = 0; l < 4; l++) {        // B: 256 rows x 8 groups
            int j = tid * 4 + l;
            int row = j >> 3, g = j & 7;
            uint32_t off = swz(row, g);
            const size_t bk = (size_t)(brow0 + row) * 1024 + ch * 64 + g * 8;
            cp16(sb + 16384 + off, g_wdh + bk, 16);
        }
    };

    const int lane = tid & 31, w = tid >> 5;
    const int wm = w >> 2, wn = w & 3;
    const int gid = lane >> 2, qid = lane & 3;

    uint32_t aoff[2][4], boff[4][4];
    #pragma unroll
    for (int mi = 0; mi < 2; mi++)
        #pragma unroll
        for (int s16 = 0; s16 < 4; s16++) {
            int row = wm * 32 + mi * 16 + (lane & 15);
            aoff[mi][s16] = swz(row, s16 * 2 + (lane >> 4));
        }
    #pragma unroll
    for (int nb = 0; nb < 4; nb++)
        #pragma unroll
        for (int s16 = 0; s16 < 4; s16++) {
            int rown = wn * 64 + nb * 16 + (lane & 7) + ((lane >> 4) << 3);
            boff[nb][s16] = swz(rown, s16 * 2 + ((lane >> 3) & 1));
        }

    float acc[2][8][4];
    #pragma unroll
    for (int mi = 0; mi < 2; mi++)
        #pragma unroll
        for (int nj = 0; nj < 8; nj++)
            #pragma unroll
            for (int q = 0; q < 4; q++) acc[mi][nj][q] = 0.f;

    load_stage(0, 0); CP_COMMIT();
    load_stage(1, 1); CP_COMMIT();

    for (int ch = 0; ch < 16; ch++) {
        CP_WAIT(1);
        __syncthreads();
        const uint32_t sb = dynu + (ch % 3) * 49152;

        #pragma unroll
        for (int s16 = 0; s16 < 4; s16++) {
            uint32_t ah[2][4];
            #pragma unroll
            for (int mi = 0; mi < 2; mi++)
                ldsm4(ah[mi], sb + aoff[mi][s16]);
            uint32_t bh[4][4];
            #pragma unroll
            for (int nb = 0; nb < 4; nb++)
                ldsm4(bh[nb], sb + 16384 + boff[nb][s16]);
            #pragma unroll
            for (int mi = 0; mi < 2; mi++)
                #pragma unroll
                for (int nj = 0; nj < 8; nj++)
                    mma16816(acc[mi][nj], ah[mi], &bh[nj >> 1][(nj & 1) * 2]);
        }

        if (ch + 2 < 16) load_stage(ch + 2, (ch + 2) % 3);
        CP_COMMIT();
    }
    CP_WAIT(0);
    __syncthreads();

    // epilogue: two 128-col fp32 passes + zero-fill other 768 cols
    float* stgf = reinterpret_cast<float*>(dynraw);
    #pragma unroll
    for (int pass = 0; pass < 2; pass++) {
        if ((wn >> 1) == pass) {
            #pragma unroll
            for (int mi = 0; mi < 2; mi++)
                #pragma unroll
                for (int nj = 0; nj < 8; nj++) {
                    int col0 = wn * 64 + nj * 8 + 2 * qid;
                    int r0 = wm * 32 + mi * 16 + gid;
                    float b0 = bsh[col0], b1 = bsh[col0 + 1];
                    int cl = col0 - pass * 128;
                    stgf[r0 * 132 + cl]           = acc[mi][nj][0] + b0;
                    stgf[r0 * 132 + cl + 1]       = acc[mi][nj][1] + b1;
                    stgf[(r0 + 8) * 132 + cl]     = acc[mi][nj][2] + b0;
                    stgf[(r0 + 8) * 132 + cl + 1] = acc[mi][nj][3] + b1;
                }
        }
        __syncthreads();
        for (int i = tid; i < 4096; i += 512) {
            int row = i >> 5, q = i & 31;
            int r = rs[row];
            if (r < 0) continue;
            float4 v = *reinterpret_cast<float4*>(&stgf[row * 132 + q * 4]);
            *reinterpret_cast<float4*>(&outp[(size_t)r * C_DIM + e * 256 + pass * 128 + q * 4]) = v;
        }
        __syncthreads();
    }
    const float4 z4 = make_float4(0.f, 0.f, 0.f, 0.f);
    for (int i = tid; i < 128 * 192; i += 512) {
        int row = i / 192, j = i - row * 192;
        int r = rs[row];
        if (r < 0) continue;
        int zcol = j * 4;
        if (zcol >= e * 256) zcol += 256;
        *reinterpret_cast<float4*>(&outp[(size_t)r * C_DIM + zcol]) = z4;
    }
}

// ---------------------------------------------------------------------------
extern "C" void kernel_launch(void* const* d_in, const int* in_sizes, int n_in,
                              void* d_out, int out_size) {
    const float* x      = (const float*)d_in[0];
    const float* w_up   = (const float*)d_in[1];
    const float* b_up   = (const float*)d_in[2];
    const float* w_down = (const float*)d_in[3];
    const float* b_down = (const float*)d_in[4];
    float* out = (float*)d_out;

    const size_t out_elems = (size_t)N_ROWS * C_DIM;
    int write_gate = (out_size >= (int)(out_elems + (size_t)N_ROWS * NTILES)) ? 1 : 0;

    static int attr_done = 0;
    if (!attr_done) {
        cudaFuncSetAttribute(gemm_up_kernel,   cudaFuncAttributeMaxDynamicSharedMemorySize, 98304);
        cudaFuncSetAttribute(gemm_down_kernel, cudaFuncAttributeMaxDynamicSharedMemorySize, 147456);
        attr_done = 1;
    }

    sig_sum_kernel<<<1024, 128>>>(w_up);                               // 0
    sign_kernel<<<16, 256>>>();                                        // 1
    route_kernel<<<N_ROWS, 128>>>(x, out + out_elems, write_gate);     // 2
    gemm_up_kernel<<<dim3(8, 128, NTILES), 256, 98304>>>(b_up);        // 3 (profiled)
    split_wdown_kernel<<<1024, 256>>>(w_down);                         // 4
    gemm_down_kernel<<<dim3(1, 128, NTILES), 512, 147456>>>(b_down, out); // 5
}